// round 5
// baseline (speedup 1.0000x reference)
#include <cuda_runtime.h>
#include <stdint.h>

#define NMAX 200000
#define EMAX 400000
#define GMAX 8192
#define HMAX 256
#define BN_EPS 1e-5f

// ---------------- scratch (device globals: no allocation allowed) ----------
__device__ float g_dis[NMAX];
__device__ float g_hw[(size_t)NMAX * HMAX];
__device__ float g_agg[(size_t)NMAX * HMAX];
__device__ float g_colsum[HMAX];
__device__ float g_colsumsq[HMAX];
__device__ float g_scale[HMAX];
__device__ float g_shift[HMAX];
__device__ float g_pm[(size_t)GMAX * HMAX];
// CSR / pooling structures
__device__ int g_rowcnt[NMAX];
__device__ int g_rowptr[NMAX + 1];
__device__ int g_fill[NMAX];
__device__ int g_esrc[EMAX];
__device__ int g_gcnt[GMAX];
__device__ int g_gptr[GMAX + 1];
__device__ int g_bsum[1024];
__device__ int g_boff[1024];
__device__ int g_dummy[4];

// ---------------- small utility kernels ------------------------------------
__global__ void k_zero_int(int* p, int n) {
    int i = blockIdx.x * blockDim.x + threadIdx.x;
    if (i < n) p[i] = 0;
}

__global__ void k_set_int(int* p, int v) { *p = v; }

__global__ void k_count(const int* __restrict__ idx, int* __restrict__ cnt, int n) {
    int i = blockIdx.x * blockDim.x + threadIdx.x;
    if (i < n) atomicAdd(&cnt[idx[i]], 1);
}

__global__ void k_dis(const int* __restrict__ cnt, float* __restrict__ dis, int n) {
    int i = blockIdx.x * blockDim.x + threadIdx.x;
    if (i < n) dis[i] = rsqrtf((float)cnt[i] + 1.0f);   // +1 = self loop
}

// ---------------- 2-level exclusive scan (chunk = 1024) ---------------------
__global__ void k_scan1(const int* __restrict__ in, int n, int* __restrict__ out,
                        int* __restrict__ bsum) {
    __shared__ int sh[256];
    int t = threadIdx.x;
    int base = blockIdx.x * 1024 + t * 4;
    int v0 = (base + 0 < n) ? in[base + 0] : 0;
    int v1 = (base + 1 < n) ? in[base + 1] : 0;
    int v2 = (base + 2 < n) ? in[base + 2] : 0;
    int v3 = (base + 3 < n) ? in[base + 3] : 0;
    int s = v0 + v1 + v2 + v3;
    sh[t] = s;
    __syncthreads();
    for (int off = 1; off < 256; off <<= 1) {
        int x = (t >= off) ? sh[t - off] : 0;
        __syncthreads();
        sh[t] += x;
        __syncthreads();
    }
    int run = sh[t] - s;   // exclusive prefix of this thread
    if (base + 0 < n) out[base + 0] = run; run += v0;
    if (base + 1 < n) out[base + 1] = run; run += v1;
    if (base + 2 < n) out[base + 2] = run; run += v2;
    if (base + 3 < n) out[base + 3] = run;
    if (t == 0) bsum[blockIdx.x] = sh[255];
}

__global__ void k_scan_add(int* __restrict__ out, const int* __restrict__ boff, int n) {
    int i = blockIdx.x * blockDim.x + threadIdx.x;
    if (i < n) out[i] += boff[i >> 10];
}

// ---------------- CSR fill ---------------------------------------------------
__global__ void k_csr_fill(const int* __restrict__ src, const int* __restrict__ dst,
                           const int* __restrict__ rowptr, int* __restrict__ fill,
                           int* __restrict__ esrc, int E) {
    int e = blockIdx.x * blockDim.x + threadIdx.x;
    if (e < E) {
        int d = dst[e];
        int pos = rowptr[d] + atomicAdd(&fill[d], 1);
        esrc[pos] = src[e];
    }
}

// ---------------- layer-1 GEMM: [N,9] @ [9,128] -----------------------------
__global__ void k_gemm1(const float* __restrict__ x, const float* __restrict__ W,
                        float* __restrict__ out, int N) {
    __shared__ float Ws[9 * 128];
    __shared__ float xs[8 * 9];
    int tid = threadIdx.x;
    for (int i = tid; i < 9 * 128; i += 256) Ws[i] = W[i];
    int r0 = blockIdx.x * 8;
    if (tid < 72) {
        int rr = tid / 9, cc = tid % 9;
        int r = r0 + rr;
        xs[tid] = (r < N) ? x[(size_t)r * 9 + cc] : 0.0f;
    }
    __syncthreads();
    int lr = tid >> 5;
    int c4 = (tid & 31) * 4;
    int r = r0 + lr;
    if (r >= N) return;
    float a0 = 0.f, a1 = 0.f, a2 = 0.f, a3 = 0.f;
#pragma unroll
    for (int k = 0; k < 9; k++) {
        float xv = xs[lr * 9 + k];
        const float* w = &Ws[k * 128 + c4];
        a0 += xv * w[0]; a1 += xv * w[1]; a2 += xv * w[2]; a3 += xv * w[3];
    }
    *(float4*)&out[(size_t)r * 128 + c4] = make_float4(a0, a1, a2, a3);
}

// ---------------- CSR gather: agg[d] = dis[d]*(sum_e dis[s]*hw[s] + dis[d]*hw[d])
template <int H>
__global__ void k_gather(const float* __restrict__ hw, const float* __restrict__ dis,
                         const int* __restrict__ rowptr, const int* __restrict__ esrc,
                         float* __restrict__ agg, int N) {
    int warp = (blockIdx.x * blockDim.x + threadIdx.x) >> 5;
    int lane = threadIdx.x & 31;
    if (warp >= N) return;
    int d = warp;
    constexpr int V = H / 128;            // float4 per lane
    int c = lane * (H / 32);
    float4 acc[V];
#pragma unroll
    for (int v = 0; v < V; v++) acc[v] = make_float4(0.f, 0.f, 0.f, 0.f);
    int e0 = rowptr[d], e1 = rowptr[d + 1];
    for (int e = e0; e < e1; e++) {
        int s = esrc[e];
        float w = dis[s];
        const float* row = &hw[(size_t)s * H + c];
#pragma unroll
        for (int v = 0; v < V; v++) {
            float4 x = *(const float4*)&row[v * 4];
            acc[v].x += w * x.x; acc[v].y += w * x.y;
            acc[v].z += w * x.z; acc[v].w += w * x.w;
        }
    }
    float dd = dis[d];
    const float* self = &hw[(size_t)d * H + c];
    float* outp = &agg[(size_t)d * H + c];
#pragma unroll
    for (int v = 0; v < V; v++) {
        float4 x = *(const float4*)&self[v * 4];
        float4 r;
        r.x = dd * (acc[v].x + dd * x.x);
        r.y = dd * (acc[v].y + dd * x.y);
        r.z = dd * (acc[v].z + dd * x.z);
        r.w = dd * (acc[v].w + dd * x.w);
        *(float4*)&outp[v * 4] = r;
    }
}

// ---------------- BN stats ---------------------------------------------------
__global__ void k_stats(const float* __restrict__ agg, int N, int H) {
    int c = threadIdx.x;
    float s = 0.f, ss = 0.f;
    for (int r = blockIdx.x; r < N; r += gridDim.x) {
        float v = agg[(size_t)r * H + c];
        s += v; ss += v * v;
    }
    atomicAdd(&g_colsum[c], s);
    atomicAdd(&g_colsumsq[c], ss);
}

__global__ void k_zero_stats(int H) {
    int c = threadIdx.x;
    if (c < H) { g_colsum[c] = 0.f; g_colsumsq[c] = 0.f; }
}

__global__ void k_finalize_bn(const float* __restrict__ gam, const float* __restrict__ bet,
                              int N, int H) {
    int c = threadIdx.x;
    if (c >= H) return;
    float inv = 1.0f / (float)N;
    float mean = g_colsum[c] * inv;
    float var = fmaxf(g_colsumsq[c] * inv - mean * mean, 0.f);
    float sc = gam[c] * rsqrtf(var + BN_EPS);
    g_scale[c] = sc;
    g_shift[c] = bet[c] - mean * sc;
}

// ---------------- SGEMM with packed f32x2 FMA --------------------------------
__device__ __forceinline__ unsigned long long dup_f32x2(float a) {
    unsigned long long r;
    unsigned int u = __float_as_uint(a);
    asm("mov.b64 %0, {%1, %1};" : "=l"(r) : "r"(u));
    return r;
}
__device__ __forceinline__ void fma2(unsigned long long& acc, unsigned long long a,
                                     unsigned long long b) {
    asm("fma.rn.f32x2 %0, %1, %2, %0;" : "+l"(acc) : "l"(a), "l"(b));
}

union F4U2 { float4 f; unsigned long long u[2]; };

template <bool BN, bool BIAS>
__global__ void __launch_bounds__(256)
k_sgemm(const float* __restrict__ A, const float* __restrict__ W,
        float* __restrict__ C, int M, int K, int Nc,
        const float* __restrict__ scale, const float* __restrict__ shift,
        const float* __restrict__ bias) {
    __shared__ float As[16][132];
    __shared__ float Ws[16][128];

    int tid = threadIdx.x;
    int tx = tid & 15;
    int ty = tid >> 4;
    int rowBase = blockIdx.y * 128;
    int colBase = blockIdx.x * 128;

    unsigned long long acc2[8][4];
#pragma unroll
    for (int i = 0; i < 8; i++)
#pragma unroll
        for (int j = 0; j < 4; j++) acc2[i][j] = 0ULL;

    for (int k0 = 0; k0 < K; k0 += 16) {
#pragma unroll
        for (int l = 0; l < 2; l++) {
            int lin = tid + l * 256;
            int ar = lin >> 2;
            int ac = (lin & 3) * 4;
            int r = rowBase + ar;
            float4 v = make_float4(0.f, 0.f, 0.f, 0.f);
            if (r < M) v = *(const float4*)&A[(size_t)r * K + k0 + ac];
            if (BN) {
                v.x = fmaxf(v.x * scale[k0 + ac + 0] + shift[k0 + ac + 0], 0.f);
                v.y = fmaxf(v.y * scale[k0 + ac + 1] + shift[k0 + ac + 1], 0.f);
                v.z = fmaxf(v.z * scale[k0 + ac + 2] + shift[k0 + ac + 2], 0.f);
                v.w = fmaxf(v.w * scale[k0 + ac + 3] + shift[k0 + ac + 3], 0.f);
            }
            As[ac + 0][ar] = v.x; As[ac + 1][ar] = v.y;
            As[ac + 2][ar] = v.z; As[ac + 3][ar] = v.w;
        }
#pragma unroll
        for (int l = 0; l < 2; l++) {
            int lin = tid + l * 256;
            int wr = lin >> 5;
            int wc = (lin & 31) * 4;
            *(float4*)&Ws[wr][wc] = *(const float4*)&W[(size_t)(k0 + wr) * Nc + colBase + wc];
        }
        __syncthreads();
#pragma unroll
        for (int k = 0; k < 16; k++) {
            F4U2 a0, a1, b0, b1;
            a0.f = *(float4*)&As[k][ty * 8];
            a1.f = *(float4*)&As[k][ty * 8 + 4];
            b0.f = *(float4*)&Ws[k][tx * 8];
            b1.f = *(float4*)&Ws[k][tx * 8 + 4];
            float av[8] = {a0.f.x, a0.f.y, a0.f.z, a0.f.w, a1.f.x, a1.f.y, a1.f.z, a1.f.w};
            unsigned long long bp[4] = {b0.u[0], b0.u[1], b1.u[0], b1.u[1]};
#pragma unroll
            for (int i = 0; i < 8; i++) {
                unsigned long long ad = dup_f32x2(av[i]);
#pragma unroll
                for (int jp = 0; jp < 4; jp++) fma2(acc2[i][jp], ad, bp[jp]);
            }
        }
        __syncthreads();
    }

#pragma unroll
    for (int i = 0; i < 8; i++) {
        int r = rowBase + ty * 8 + i;
        if (r >= M) continue;
#pragma unroll
        for (int jp = 0; jp < 4; jp += 2) {
            int c = colBase + tx * 8 + jp * 2;
            unsigned long long u0 = acc2[i][jp], u1 = acc2[i][jp + 1];
            float4 v;
            v.x = __uint_as_float((unsigned)u0);
            v.y = __uint_as_float((unsigned)(u0 >> 32));
            v.z = __uint_as_float((unsigned)u1);
            v.w = __uint_as_float((unsigned)(u1 >> 32));
            if (BIAS) { v.x += bias[c]; v.y += bias[c + 1]; v.z += bias[c + 2]; v.w += bias[c + 3]; }
            *(float4*)&C[(size_t)r * Nc + c] = v;
        }
    }
}

// ---------------- segmented pooling (batch sorted) ---------------------------
__global__ void k_pool(const float* __restrict__ agg, const int* __restrict__ gptr,
                       float* __restrict__ pm) {
    int g = blockIdx.x;
    int c = threadIdx.x;      // 256
    int r0 = gptr[g], r1 = gptr[g + 1];
    float sc = g_scale[c], sh = g_shift[c];
    float s = 0.f;
    for (int r = r0; r < r1; r++) {
        float v = agg[(size_t)r * 256 + c];
        s += fmaxf(v * sc + sh, 0.f);
    }
    float cnt = (float)(r1 - r0);
    pm[(size_t)g * 256 + c] = s / fmaxf(cnt, 1.0f);
}

// ---------------- host driver ------------------------------------------------
static void exclusive_scan(int* data_in, int n, int* out, int* bsum, int* boff, int* dummy) {
    int nb = (n + 1023) / 1024;
    k_scan1<<<nb, 256>>>(data_in, n, out, bsum);
    k_scan1<<<1, 256>>>(bsum, nb, boff, dummy);
    k_scan_add<<<(n + 255) / 256, 256>>>(out, boff, n);
}

extern "C" void kernel_launch(void* const* d_in, const int* in_sizes, int n_in,
                              void* d_out, int out_size) {
    const float* x = (const float*)d_in[0];
    const int* ei = (const int*)d_in[1];
    const int* batch = (const int*)d_in[2];
    int o = (in_sizes[3] == 1) ? 4 : 3;
    const float* W1 = (const float*)d_in[o + 0];
    const float* gm1 = (const float*)d_in[o + 2];
    const float* be1 = (const float*)d_in[o + 3];
    const float* W2 = (const float*)d_in[o + 4];
    const float* gm2 = (const float*)d_in[o + 6];
    const float* be2 = (const float*)d_in[o + 7];
    const float* W3 = (const float*)d_in[o + 8];
    const float* gm3 = (const float*)d_in[o + 10];
    const float* be3 = (const float*)d_in[o + 11];
    const float* Wp = (const float*)d_in[o + 12];
    const float* bp = (const float*)d_in[o + 13];

    int N = in_sizes[0] / 9;
    int E = in_sizes[1] / 2;
    int P = in_sizes[o + 13];
    int G = out_size / P;

    float *dis, *hw, *agg, *pm, *scale, *shift;
    int *rowcnt, *rowptr, *fill, *esrc, *gcnt, *gptr, *bsum, *boff, *dummy;
    cudaGetSymbolAddress((void**)&dis, g_dis);
    cudaGetSymbolAddress((void**)&hw, g_hw);
    cudaGetSymbolAddress((void**)&agg, g_agg);
    cudaGetSymbolAddress((void**)&pm, g_pm);
    cudaGetSymbolAddress((void**)&scale, g_scale);
    cudaGetSymbolAddress((void**)&shift, g_shift);
    cudaGetSymbolAddress((void**)&rowcnt, g_rowcnt);
    cudaGetSymbolAddress((void**)&rowptr, g_rowptr);
    cudaGetSymbolAddress((void**)&fill, g_fill);
    cudaGetSymbolAddress((void**)&esrc, g_esrc);
    cudaGetSymbolAddress((void**)&gcnt, g_gcnt);
    cudaGetSymbolAddress((void**)&gptr, g_gptr);
    cudaGetSymbolAddress((void**)&bsum, g_bsum);
    cudaGetSymbolAddress((void**)&boff, g_boff);
    cudaGetSymbolAddress((void**)&dummy, g_dummy);

    const int* src = ei;
    const int* dst = ei + E;

    // ---- CSR build + norm ----
    k_zero_int<<<(N + 255) / 256, 256>>>(rowcnt, N);
    k_count<<<(E + 255) / 256, 256>>>(dst, rowcnt, E);
    k_dis<<<(N + 255) / 256, 256>>>(rowcnt, dis, N);
    exclusive_scan(rowcnt, N, rowptr, bsum, boff, dummy);
    k_set_int<<<1, 1>>>(rowptr + N, E);
    k_zero_int<<<(N + 255) / 256, 256>>>(fill, N);
    k_csr_fill<<<(E + 255) / 256, 256>>>(src, dst, rowptr, fill, esrc, E);

    // ---- graph segment ptrs (batch is sorted) ----
    k_zero_int<<<(G + 255) / 256, 256>>>(gcnt, G);
    k_count<<<(N + 255) / 256, 256>>>(batch, gcnt, N);
    exclusive_scan(gcnt, G, gptr, bsum, boff, dummy);
    k_set_int<<<1, 1>>>(gptr + G, N);

    // ---- layer 1: x@W1 -> gather -> BN params (linear bias cancels in BN) ----
    k_gemm1<<<(N + 7) / 8, 256>>>(x, W1, hw, N);
    k_gather<128><<<(N + 7) / 8, 256>>>(hw, dis, rowptr, esrc, agg, N);
    k_zero_stats<<<1, 128>>>(128);
    k_stats<<<1024, 128>>>(agg, N, 128);
    k_finalize_bn<<<1, 128>>>(gm1, be1, N, 128);

    // ---- layer 2 ----
    {
        dim3 grid(2, (N + 127) / 128);
        k_sgemm<true, false><<<grid, 256>>>(agg, W2, hw, N, 128, 256, scale, shift, nullptr);
    }
    k_gather<256><<<(N + 7) / 8, 256>>>(hw, dis, rowptr, esrc, agg, N);
    k_zero_stats<<<1, 256>>>(256);
    k_stats<<<1024, 256>>>(agg, N, 256);
    k_finalize_bn<<<1, 256>>>(gm2, be2, N, 256);

    // ---- layer 3 ----
    {
        dim3 grid(2, (N + 127) / 128);
        k_sgemm<true, false><<<grid, 256>>>(agg, W3, hw, N, 256, 256, scale, shift, nullptr);
    }
    k_gather<256><<<(N + 7) / 8, 256>>>(hw, dis, rowptr, esrc, agg, N);
    k_zero_stats<<<1, 256>>>(256);
    k_stats<<<1024, 256>>>(agg, N, 256);
    k_finalize_bn<<<1, 256>>>(gm3, be3, N, 256);

    // ---- pooling (BN3 + relu fused, segmented, no atomics) ----
    k_pool<<<G, 256>>>(agg, gptr, pm);

    // ---- head: pm @ Wp + bp -> d_out ----
    {
        dim3 grid(P / 128, (G + 127) / 128);
        k_sgemm<false, true><<<grid, 256>>>(pm, Wp, (float*)d_out, G, 256, P,
                                            nullptr, nullptr, bp);
    }
}

// round 6
// speedup vs baseline: 1.0003x; 1.0003x over previous
#include <cuda_runtime.h>
#include <stdint.h>

#define NMAX 200000
#define EMAX 400000
#define GMAX 8192
#define HMAX 256
#define BN_EPS 1e-5f

// ---------------- scratch (device globals: no allocation allowed) ----------
__device__ float g_dis[NMAX];
__device__ float g_hw[(size_t)NMAX * HMAX];
__device__ float g_agg[(size_t)NMAX * HMAX];
__device__ float g_colsum[HMAX];
__device__ float g_colsumsq[HMAX];
__device__ float g_scale[HMAX];
__device__ float g_shift[HMAX];
__device__ float g_pm[(size_t)GMAX * HMAX];
// CSR / pooling structures
__device__ int g_rowcnt[NMAX];
__device__ int g_rowptr[NMAX + 1];
__device__ int g_fill[NMAX];
__device__ int g_esrc[EMAX];
__device__ int g_gcnt[GMAX];
__device__ int g_gptr[GMAX + 1];
__device__ int g_bsum[1024];
__device__ int g_boff[1024];
__device__ int g_dummy[4];

// ---------------- small utility kernels ------------------------------------
__global__ void k_zero_int(int* p, int n) {
    int i = blockIdx.x * blockDim.x + threadIdx.x;
    if (i < n) p[i] = 0;
}

__global__ void k_set_int(int* p, int v) { *p = v; }

__global__ void k_count(const int* __restrict__ idx, int* __restrict__ cnt, int n) {
    int i = blockIdx.x * blockDim.x + threadIdx.x;
    if (i < n) atomicAdd(&cnt[idx[i]], 1);
}

__global__ void k_dis(const int* __restrict__ cnt, float* __restrict__ dis, int n) {
    int i = blockIdx.x * blockDim.x + threadIdx.x;
    if (i < n) dis[i] = rsqrtf((float)cnt[i] + 1.0f);   // +1 = self loop
}

// ---------------- 2-level exclusive scan (chunk = 1024) ---------------------
__global__ void k_scan1(const int* __restrict__ in, int n, int* __restrict__ out,
                        int* __restrict__ bsum) {
    __shared__ int sh[256];
    int t = threadIdx.x;
    int base = blockIdx.x * 1024 + t * 4;
    int v0 = (base + 0 < n) ? in[base + 0] : 0;
    int v1 = (base + 1 < n) ? in[base + 1] : 0;
    int v2 = (base + 2 < n) ? in[base + 2] : 0;
    int v3 = (base + 3 < n) ? in[base + 3] : 0;
    int s = v0 + v1 + v2 + v3;
    sh[t] = s;
    __syncthreads();
    for (int off = 1; off < 256; off <<= 1) {
        int x = (t >= off) ? sh[t - off] : 0;
        __syncthreads();
        sh[t] += x;
        __syncthreads();
    }
    int run = sh[t] - s;   // exclusive prefix of this thread
    if (base + 0 < n) out[base + 0] = run; run += v0;
    if (base + 1 < n) out[base + 1] = run; run += v1;
    if (base + 2 < n) out[base + 2] = run; run += v2;
    if (base + 3 < n) out[base + 3] = run;
    if (t == 0) bsum[blockIdx.x] = sh[255];
}

__global__ void k_scan_add(int* __restrict__ out, const int* __restrict__ boff, int n) {
    int i = blockIdx.x * blockDim.x + threadIdx.x;
    if (i < n) out[i] += boff[i >> 10];
}

// ---------------- CSR fill ---------------------------------------------------
__global__ void k_csr_fill(const int* __restrict__ src, const int* __restrict__ dst,
                           const int* __restrict__ rowptr, int* __restrict__ fill,
                           int* __restrict__ esrc, int E) {
    int e = blockIdx.x * blockDim.x + threadIdx.x;
    if (e < E) {
        int d = dst[e];
        int pos = rowptr[d] + atomicAdd(&fill[d], 1);
        esrc[pos] = src[e];
    }
}

// ---------------- layer-1 GEMM: [N,9] @ [9,128] -----------------------------
__global__ void k_gemm1(const float* __restrict__ x, const float* __restrict__ W,
                        float* __restrict__ out, int N) {
    __shared__ float Ws[9 * 128];
    __shared__ float xs[8 * 9];
    int tid = threadIdx.x;
    for (int i = tid; i < 9 * 128; i += 256) Ws[i] = W[i];
    int r0 = blockIdx.x * 8;
    if (tid < 72) {
        int rr = tid / 9, cc = tid % 9;
        int r = r0 + rr;
        xs[tid] = (r < N) ? x[(size_t)r * 9 + cc] : 0.0f;
    }
    __syncthreads();
    int lr = tid >> 5;
    int c4 = (tid & 31) * 4;
    int r = r0 + lr;
    if (r >= N) return;
    float a0 = 0.f, a1 = 0.f, a2 = 0.f, a3 = 0.f;
#pragma unroll
    for (int k = 0; k < 9; k++) {
        float xv = xs[lr * 9 + k];
        const float* w = &Ws[k * 128 + c4];
        a0 += xv * w[0]; a1 += xv * w[1]; a2 += xv * w[2]; a3 += xv * w[3];
    }
    *(float4*)&out[(size_t)r * 128 + c4] = make_float4(a0, a1, a2, a3);
}

// ---------------- CSR gather: agg[d] = dis[d]*(sum_e dis[s]*hw[s] + dis[d]*hw[d])
template <int H>
__global__ void k_gather(const float* __restrict__ hw, const float* __restrict__ dis,
                         const int* __restrict__ rowptr, const int* __restrict__ esrc,
                         float* __restrict__ agg, int N) {
    int warp = (blockIdx.x * blockDim.x + threadIdx.x) >> 5;
    int lane = threadIdx.x & 31;
    if (warp >= N) return;
    int d = warp;
    constexpr int V = H / 128;            // float4 per lane
    int c = lane * (H / 32);
    float4 acc[V];
#pragma unroll
    for (int v = 0; v < V; v++) acc[v] = make_float4(0.f, 0.f, 0.f, 0.f);
    int e0 = rowptr[d], e1 = rowptr[d + 1];
    for (int e = e0; e < e1; e++) {
        int s = esrc[e];
        float w = dis[s];
        const float* row = &hw[(size_t)s * H + c];
#pragma unroll
        for (int v = 0; v < V; v++) {
            float4 x = *(const float4*)&row[v * 4];
            acc[v].x += w * x.x; acc[v].y += w * x.y;
            acc[v].z += w * x.z; acc[v].w += w * x.w;
        }
    }
    float dd = dis[d];
    const float* self = &hw[(size_t)d * H + c];
    float* outp = &agg[(size_t)d * H + c];
#pragma unroll
    for (int v = 0; v < V; v++) {
        float4 x = *(const float4*)&self[v * 4];
        float4 r;
        r.x = dd * (acc[v].x + dd * x.x);
        r.y = dd * (acc[v].y + dd * x.y);
        r.z = dd * (acc[v].z + dd * x.z);
        r.w = dd * (acc[v].w + dd * x.w);
        *(float4*)&outp[v * 4] = r;
    }
}

// ---------------- BN stats ---------------------------------------------------
__global__ void k_stats(const float* __restrict__ agg, int N, int H) {
    int c = threadIdx.x;
    float s = 0.f, ss = 0.f;
    for (int r = blockIdx.x; r < N; r += gridDim.x) {
        float v = agg[(size_t)r * H + c];
        s += v; ss += v * v;
    }
    atomicAdd(&g_colsum[c], s);
    atomicAdd(&g_colsumsq[c], ss);
}

__global__ void k_zero_stats(int H) {
    int c = threadIdx.x;
    if (c < H) { g_colsum[c] = 0.f; g_colsumsq[c] = 0.f; }
}

__global__ void k_finalize_bn(const float* __restrict__ gam, const float* __restrict__ bet,
                              int N, int H) {
    int c = threadIdx.x;
    if (c >= H) return;
    float inv = 1.0f / (float)N;
    float mean = g_colsum[c] * inv;
    float var = fmaxf(g_colsumsq[c] * inv - mean * mean, 0.f);
    float sc = gam[c] * rsqrtf(var + BN_EPS);
    g_scale[c] = sc;
    g_shift[c] = bet[c] - mean * sc;
}

// ---------------- SGEMM with packed f32x2 FMA --------------------------------
__device__ __forceinline__ unsigned long long dup_f32x2(float a) {
    unsigned long long r;
    unsigned int u = __float_as_uint(a);
    asm("mov.b64 %0, {%1, %1};" : "=l"(r) : "r"(u));
    return r;
}
__device__ __forceinline__ void fma2(unsigned long long& acc, unsigned long long a,
                                     unsigned long long b) {
    asm("fma.rn.f32x2 %0, %1, %2, %0;" : "+l"(acc) : "l"(a), "l"(b));
}

union F4U2 { float4 f; unsigned long long u[2]; };

template <bool BN, bool BIAS>
__global__ void __launch_bounds__(256)
k_sgemm(const float* __restrict__ A, const float* __restrict__ W,
        float* __restrict__ C, int M, int K, int Nc,
        const float* __restrict__ scale, const float* __restrict__ shift,
        const float* __restrict__ bias) {
    __shared__ float As[16][132];
    __shared__ float Ws[16][128];

    int tid = threadIdx.x;
    int tx = tid & 15;
    int ty = tid >> 4;
    int rowBase = blockIdx.y * 128;
    int colBase = blockIdx.x * 128;

    unsigned long long acc2[8][4];
#pragma unroll
    for (int i = 0; i < 8; i++)
#pragma unroll
        for (int j = 0; j < 4; j++) acc2[i][j] = 0ULL;

    for (int k0 = 0; k0 < K; k0 += 16) {
#pragma unroll
        for (int l = 0; l < 2; l++) {
            int lin = tid + l * 256;
            int ar = lin >> 2;
            int ac = (lin & 3) * 4;
            int r = rowBase + ar;
            float4 v = make_float4(0.f, 0.f, 0.f, 0.f);
            if (r < M) v = *(const float4*)&A[(size_t)r * K + k0 + ac];
            if (BN) {
                v.x = fmaxf(v.x * scale[k0 + ac + 0] + shift[k0 + ac + 0], 0.f);
                v.y = fmaxf(v.y * scale[k0 + ac + 1] + shift[k0 + ac + 1], 0.f);
                v.z = fmaxf(v.z * scale[k0 + ac + 2] + shift[k0 + ac + 2], 0.f);
                v.w = fmaxf(v.w * scale[k0 + ac + 3] + shift[k0 + ac + 3], 0.f);
            }
            As[ac + 0][ar] = v.x; As[ac + 1][ar] = v.y;
            As[ac + 2][ar] = v.z; As[ac + 3][ar] = v.w;
        }
#pragma unroll
        for (int l = 0; l < 2; l++) {
            int lin = tid + l * 256;
            int wr = lin >> 5;
            int wc = (lin & 31) * 4;
            *(float4*)&Ws[wr][wc] = *(const float4*)&W[(size_t)(k0 + wr) * Nc + colBase + wc];
        }
        __syncthreads();
#pragma unroll
        for (int k = 0; k < 16; k++) {
            F4U2 a0, a1, b0, b1;
            a0.f = *(float4*)&As[k][ty * 8];
            a1.f = *(float4*)&As[k][ty * 8 + 4];
            b0.f = *(float4*)&Ws[k][tx * 8];
            b1.f = *(float4*)&Ws[k][tx * 8 + 4];
            float av[8] = {a0.f.x, a0.f.y, a0.f.z, a0.f.w, a1.f.x, a1.f.y, a1.f.z, a1.f.w};
            unsigned long long bp[4] = {b0.u[0], b0.u[1], b1.u[0], b1.u[1]};
#pragma unroll
            for (int i = 0; i < 8; i++) {
                unsigned long long ad = dup_f32x2(av[i]);
#pragma unroll
                for (int jp = 0; jp < 4; jp++) fma2(acc2[i][jp], ad, bp[jp]);
            }
        }
        __syncthreads();
    }

#pragma unroll
    for (int i = 0; i < 8; i++) {
        int r = rowBase + ty * 8 + i;
        if (r >= M) continue;
#pragma unroll
        for (int jp = 0; jp < 4; jp += 2) {
            int c = colBase + tx * 8 + jp * 2;
            unsigned long long u0 = acc2[i][jp], u1 = acc2[i][jp + 1];
            float4 v;
            v.x = __uint_as_float((unsigned)u0);
            v.y = __uint_as_float((unsigned)(u0 >> 32));
            v.z = __uint_as_float((unsigned)u1);
            v.w = __uint_as_float((unsigned)(u1 >> 32));
            if (BIAS) { v.x += bias[c]; v.y += bias[c + 1]; v.z += bias[c + 2]; v.w += bias[c + 3]; }
            *(float4*)&C[(size_t)r * Nc + c] = v;
        }
    }
}

// ---------------- segmented pooling (batch sorted) ---------------------------
__global__ void k_pool(const float* __restrict__ agg, const int* __restrict__ gptr,
                       float* __restrict__ pm) {
    int g = blockIdx.x;
    int c = threadIdx.x;      // 256
    int r0 = gptr[g], r1 = gptr[g + 1];
    float sc = g_scale[c], sh = g_shift[c];
    float s = 0.f;
    for (int r = r0; r < r1; r++) {
        float v = agg[(size_t)r * 256 + c];
        s += fmaxf(v * sc + sh, 0.f);
    }
    float cnt = (float)(r1 - r0);
    pm[(size_t)g * 256 + c] = s / fmaxf(cnt, 1.0f);
}

// ---------------- host driver ------------------------------------------------
static void exclusive_scan(int* data_in, int n, int* out, int* bsum, int* boff, int* dummy) {
    int nb = (n + 1023) / 1024;
    k_scan1<<<nb, 256>>>(data_in, n, out, bsum);
    k_scan1<<<1, 256>>>(bsum, nb, boff, dummy);
    k_scan_add<<<(n + 255) / 256, 256>>>(out, boff, n);
}

extern "C" void kernel_launch(void* const* d_in, const int* in_sizes, int n_in,
                              void* d_out, int out_size) {
    const float* x = (const float*)d_in[0];
    const int* ei = (const int*)d_in[1];
    const int* batch = (const int*)d_in[2];
    int o = (in_sizes[3] == 1) ? 4 : 3;
    const float* W1 = (const float*)d_in[o + 0];
    const float* gm1 = (const float*)d_in[o + 2];
    const float* be1 = (const float*)d_in[o + 3];
    const float* W2 = (const float*)d_in[o + 4];
    const float* gm2 = (const float*)d_in[o + 6];
    const float* be2 = (const float*)d_in[o + 7];
    const float* W3 = (const float*)d_in[o + 8];
    const float* gm3 = (const float*)d_in[o + 10];
    const float* be3 = (const float*)d_in[o + 11];
    const float* Wp = (const float*)d_in[o + 12];
    const float* bp = (const float*)d_in[o + 13];

    int N = in_sizes[0] / 9;
    int E = in_sizes[1] / 2;
    int P = in_sizes[o + 13];
    int G = out_size / P;

    float *dis, *hw, *agg, *pm, *scale, *shift;
    int *rowcnt, *rowptr, *fill, *esrc, *gcnt, *gptr, *bsum, *boff, *dummy;
    cudaGetSymbolAddress((void**)&dis, g_dis);
    cudaGetSymbolAddress((void**)&hw, g_hw);
    cudaGetSymbolAddress((void**)&agg, g_agg);
    cudaGetSymbolAddress((void**)&pm, g_pm);
    cudaGetSymbolAddress((void**)&scale, g_scale);
    cudaGetSymbolAddress((void**)&shift, g_shift);
    cudaGetSymbolAddress((void**)&rowcnt, g_rowcnt);
    cudaGetSymbolAddress((void**)&rowptr, g_rowptr);
    cudaGetSymbolAddress((void**)&fill, g_fill);
    cudaGetSymbolAddress((void**)&esrc, g_esrc);
    cudaGetSymbolAddress((void**)&gcnt, g_gcnt);
    cudaGetSymbolAddress((void**)&gptr, g_gptr);
    cudaGetSymbolAddress((void**)&bsum, g_bsum);
    cudaGetSymbolAddress((void**)&boff, g_boff);
    cudaGetSymbolAddress((void**)&dummy, g_dummy);

    const int* src = ei;
    const int* dst = ei + E;

    // ---- CSR build + norm ----
    k_zero_int<<<(N + 255) / 256, 256>>>(rowcnt, N);
    k_count<<<(E + 255) / 256, 256>>>(dst, rowcnt, E);
    k_dis<<<(N + 255) / 256, 256>>>(rowcnt, dis, N);
    exclusive_scan(rowcnt, N, rowptr, bsum, boff, dummy);
    k_set_int<<<1, 1>>>(rowptr + N, E);
    k_zero_int<<<(N + 255) / 256, 256>>>(fill, N);
    k_csr_fill<<<(E + 255) / 256, 256>>>(src, dst, rowptr, fill, esrc, E);

    // ---- graph segment ptrs (batch is sorted) ----
    k_zero_int<<<(G + 255) / 256, 256>>>(gcnt, G);
    k_count<<<(N + 255) / 256, 256>>>(batch, gcnt, N);
    exclusive_scan(gcnt, G, gptr, bsum, boff, dummy);
    k_set_int<<<1, 1>>>(gptr + G, N);

    // ---- layer 1: x@W1 -> gather -> BN params (linear bias cancels in BN) ----
    k_gemm1<<<(N + 7) / 8, 256>>>(x, W1, hw, N);
    k_gather<128><<<(N + 7) / 8, 256>>>(hw, dis, rowptr, esrc, agg, N);
    k_zero_stats<<<1, 128>>>(128);
    k_stats<<<1024, 128>>>(agg, N, 128);
    k_finalize_bn<<<1, 128>>>(gm1, be1, N, 128);

    // ---- layer 2 ----
    {
        dim3 grid(2, (N + 127) / 128);
        k_sgemm<true, false><<<grid, 256>>>(agg, W2, hw, N, 128, 256, scale, shift, nullptr);
    }
    k_gather<256><<<(N + 7) / 8, 256>>>(hw, dis, rowptr, esrc, agg, N);
    k_zero_stats<<<1, 256>>>(256);
    k_stats<<<1024, 256>>>(agg, N, 256);
    k_finalize_bn<<<1, 256>>>(gm2, be2, N, 256);

    // ---- layer 3 ----
    {
        dim3 grid(2, (N + 127) / 128);
        k_sgemm<true, false><<<grid, 256>>>(agg, W3, hw, N, 256, 256, scale, shift, nullptr);
    }
    k_gather<256><<<(N + 7) / 8, 256>>>(hw, dis, rowptr, esrc, agg, N);
    k_zero_stats<<<1, 256>>>(256);
    k_stats<<<1024, 256>>>(agg, N, 256);
    k_finalize_bn<<<1, 256>>>(gm3, be3, N, 256);

    // ---- pooling (BN3 + relu fused, segmented, no atomics) ----
    k_pool<<<G, 256>>>(agg, gptr, pm);

    // ---- head: pm @ Wp + bp -> d_out ----
    {
        dim3 grid(P / 128, (G + 127) / 128);
        k_sgemm<false, true><<<grid, 256>>>(pm, Wp, (float*)d_out, G, 256, P,
                                            nullptr, nullptr, bp);
    }
}

// round 8
// speedup vs baseline: 1.1937x; 1.1934x over previous
#include <cuda_runtime.h>
#include <stdint.h>

#define NMAX 200000
#define EMAX 400000
#define GMAX 8192
#define HMAX 256
#define BN_EPS 1e-5f

// ---------------- scratch (device globals: no allocation allowed) ----------
__device__ float g_dis[NMAX];
__device__ float g_hw[(size_t)NMAX * HMAX];
__device__ float g_agg[(size_t)NMAX * HMAX];
__device__ float g_colsum[HMAX];
__device__ float g_colsumsq[HMAX];
__device__ float g_scale[HMAX];
__device__ float g_shift[HMAX];
__device__ float g_pm[(size_t)GMAX * HMAX];
__device__ int g_rowcnt[NMAX];
__device__ int g_rowptr[NMAX + 1];
__device__ int g_fill[NMAX];
__device__ int g_esrc[EMAX];
__device__ int g_gcnt[GMAX];
__device__ int g_gptr[GMAX + 1];
__device__ int g_bsum[1024];
__device__ int g_boff[1024];
__device__ int g_dummy[4];

// ---------------- small utility kernels ------------------------------------
__global__ void k_zero_int(int* p, int n) {
    int i = blockIdx.x * blockDim.x + threadIdx.x;
    if (i < n) p[i] = 0;
}
__global__ void k_set_int(int* p, int v) { *p = v; }
__global__ void k_count(const int* __restrict__ idx, int* __restrict__ cnt, int n) {
    int i = blockIdx.x * blockDim.x + threadIdx.x;
    if (i < n) atomicAdd(&cnt[idx[i]], 1);
}
__global__ void k_dis(const int* __restrict__ cnt, float* __restrict__ dis, int n) {
    int i = blockIdx.x * blockDim.x + threadIdx.x;
    if (i < n) dis[i] = rsqrtf((float)cnt[i] + 1.0f);
}

// ---------------- 2-level exclusive scan (chunk = 1024) ---------------------
__global__ void k_scan1(const int* __restrict__ in, int n, int* __restrict__ out,
                        int* __restrict__ bsum) {
    __shared__ int sh[256];
    int t = threadIdx.x;
    int base = blockIdx.x * 1024 + t * 4;
    int v0 = (base + 0 < n) ? in[base + 0] : 0;
    int v1 = (base + 1 < n) ? in[base + 1] : 0;
    int v2 = (base + 2 < n) ? in[base + 2] : 0;
    int v3 = (base + 3 < n) ? in[base + 3] : 0;
    int s = v0 + v1 + v2 + v3;
    sh[t] = s;
    __syncthreads();
    for (int off = 1; off < 256; off <<= 1) {
        int x = (t >= off) ? sh[t - off] : 0;
        __syncthreads();
        sh[t] += x;
        __syncthreads();
    }
    int run = sh[t] - s;
    if (base + 0 < n) out[base + 0] = run; run += v0;
    if (base + 1 < n) out[base + 1] = run; run += v1;
    if (base + 2 < n) out[base + 2] = run; run += v2;
    if (base + 3 < n) out[base + 3] = run;
    if (t == 0) bsum[blockIdx.x] = sh[255];
}
__global__ void k_scan_add(int* __restrict__ out, const int* __restrict__ boff, int n) {
    int i = blockIdx.x * blockDim.x + threadIdx.x;
    if (i < n) out[i] += boff[i >> 10];
}

// ---------------- CSR fill ---------------------------------------------------
__global__ void k_csr_fill(const int* __restrict__ src, const int* __restrict__ dst,
                           const int* __restrict__ rowptr, int* __restrict__ fill,
                           int* __restrict__ esrc, int E) {
    int e = blockIdx.x * blockDim.x + threadIdx.x;
    if (e < E) {
        int d = dst[e];
        int pos = rowptr[d] + atomicAdd(&fill[d], 1);
        esrc[pos] = src[e];
    }
}

// ---------------- layer-1 GEMM: [N,9] @ [9,128] -----------------------------
__global__ void k_gemm1(const float* __restrict__ x, const float* __restrict__ W,
                        float* __restrict__ out, int N) {
    __shared__ float Ws[9 * 128];
    __shared__ float xs[8 * 9];
    int tid = threadIdx.x;
    for (int i = tid; i < 9 * 128; i += 256) Ws[i] = W[i];
    int r0 = blockIdx.x * 8;
    if (tid < 72) {
        int rr = tid / 9, cc = tid % 9;
        int r = r0 + rr;
        xs[tid] = (r < N) ? x[(size_t)r * 9 + cc] : 0.0f;
    }
    __syncthreads();
    int lr = tid >> 5;
    int c4 = (tid & 31) * 4;
    int r = r0 + lr;
    if (r >= N) return;
    float a0 = 0.f, a1 = 0.f, a2 = 0.f, a3 = 0.f;
#pragma unroll
    for (int k = 0; k < 9; k++) {
        float xv = xs[lr * 9 + k];
        const float* w = &Ws[k * 128 + c4];
        a0 += xv * w[0]; a1 += xv * w[1]; a2 += xv * w[2]; a3 += xv * w[3];
    }
    *(float4*)&out[(size_t)r * 128 + c4] = make_float4(a0, a1, a2, a3);
}

// ================= tf32 mma.sync GEMM (sm_80+ baseline ISA) =================
__device__ __forceinline__ uint32_t f2tf32(float x) {
    uint32_t u; asm("cvt.rna.tf32.f32 %0, %1;" : "=r"(u) : "f"(x)); return u;
}
__device__ __forceinline__ int swz(int k) { return ((k & 3) << 3) | (k >> 2); }

__device__ __forceinline__ void mma_tf32(float4& c, uint32_t a0, uint32_t a1,
                                         uint32_t a2, uint32_t a3,
                                         uint32_t b0, uint32_t b1) {
    asm volatile(
        "mma.sync.aligned.m16n8k8.row.col.f32.tf32.tf32.f32 "
        "{%0,%1,%2,%3}, {%4,%5,%6,%7}, {%8,%9}, {%0,%1,%2,%3};"
        : "+f"(c.x), "+f"(c.y), "+f"(c.z), "+f"(c.w)
        : "r"(a0), "r"(a1), "r"(a2), "r"(a3), "r"(b0), "r"(b1));
}

// C[M,Nc] = relu(BN(A[M,K])) @ W[K,Nc]; block tile 128x128, K-chunk 32.
// SMEM word layout: idx = k*128 + (m ^ swz(k))  (conflict-free frag LDS).
template <bool BN>
__global__ void __launch_bounds__(256, 1)
k_gemm_mma(const float* __restrict__ A, const float* __restrict__ W,
           float* __restrict__ C, int M, int K, int Nc,
           const float* __restrict__ scale, const float* __restrict__ shift) {
    __shared__ uint32_t As[32 * 128];
    __shared__ uint32_t Bs[32 * 128];
    int tid = threadIdx.x;
    int lane = tid & 31, warp = tid >> 5;
    int g = lane >> 2, tig = lane & 3;
    int wm = warp & 3, wn = warp >> 2;
    int rowBase = blockIdx.y * 128;
    int colBase = blockIdx.x * 128;

    float4 acc[2][8];
#pragma unroll
    for (int i = 0; i < 2; i++)
#pragma unroll
        for (int j = 0; j < 8; j++) acc[i][j] = make_float4(0.f, 0.f, 0.f, 0.f);

    for (int k0 = 0; k0 < K; k0 += 32) {
        // ---- A tile: 128 rows x 32 k (BN+ReLU fused), coalesced float4 ----
#pragma unroll
        for (int l = 0; l < 4; l++) {
            int lin = l * 256 + tid;
            int r = lin >> 3;
            int kq = (lin & 7) * 4;
            int gr = rowBase + r;
            float4 v = make_float4(0.f, 0.f, 0.f, 0.f);
            if (gr < M) v = *(const float4*)&A[(size_t)gr * K + k0 + kq];
            if (BN) {
                v.x = fmaxf(v.x * scale[k0 + kq + 0] + shift[k0 + kq + 0], 0.f);
                v.y = fmaxf(v.y * scale[k0 + kq + 1] + shift[k0 + kq + 1], 0.f);
                v.z = fmaxf(v.z * scale[k0 + kq + 2] + shift[k0 + kq + 2], 0.f);
                v.w = fmaxf(v.w * scale[k0 + kq + 3] + shift[k0 + kq + 3], 0.f);
            }
            As[(kq + 0) * 128 + (r ^ swz(kq + 0))] = f2tf32(v.x);
            As[(kq + 1) * 128 + (r ^ swz(kq + 1))] = f2tf32(v.y);
            As[(kq + 2) * 128 + (r ^ swz(kq + 2))] = f2tf32(v.z);
            As[(kq + 3) * 128 + (r ^ swz(kq + 3))] = f2tf32(v.w);
        }
        // ---- B tile: 32 k x 128 n, coalesced float4 along n ----
#pragma unroll
        for (int l = 0; l < 4; l++) {
            int lin = l * 256 + tid;
            int k = lin >> 5;
            int n4 = (lin & 31) * 4;
            float4 w4 = *(const float4*)&W[(size_t)(k0 + k) * Nc + colBase + n4];
            int xk = swz(k);
            Bs[k * 128 + ((n4 + 0) ^ xk)] = f2tf32(w4.x);
            Bs[k * 128 + ((n4 + 1) ^ xk)] = f2tf32(w4.y);
            Bs[k * 128 + ((n4 + 2) ^ xk)] = f2tf32(w4.z);
            Bs[k * 128 + ((n4 + 3) ^ xk)] = f2tf32(w4.w);
        }
        __syncthreads();
#pragma unroll
        for (int s = 0; s < 4; s++) {
            int kA = s * 8 + tig;
            int kB = kA + 4;
            int xa = swz(kA), xb = swz(kB);
            uint32_t a[2][4];
#pragma unroll
            for (int mt = 0; mt < 2; mt++) {
                int m = wm * 32 + mt * 16 + g;
                a[mt][0] = As[kA * 128 + (m ^ xa)];
                a[mt][1] = As[kA * 128 + ((m + 8) ^ xa)];
                a[mt][2] = As[kB * 128 + (m ^ xb)];
                a[mt][3] = As[kB * 128 + ((m + 8) ^ xb)];
            }
#pragma unroll
            for (int nt = 0; nt < 8; nt++) {
                int n = wn * 64 + nt * 8 + g;
                uint32_t b0 = Bs[kA * 128 + (n ^ xa)];
                uint32_t b1 = Bs[kB * 128 + (n ^ xb)];
                mma_tf32(acc[0][nt], a[0][0], a[0][1], a[0][2], a[0][3], b0, b1);
                mma_tf32(acc[1][nt], a[1][0], a[1][1], a[1][2], a[1][3], b0, b1);
            }
        }
        __syncthreads();
    }
    // ---- epilogue ----
#pragma unroll
    for (int mt = 0; mt < 2; mt++) {
        int r0 = rowBase + wm * 32 + mt * 16 + g;
#pragma unroll
        for (int nt = 0; nt < 8; nt++) {
            int c = colBase + wn * 64 + nt * 8 + tig * 2;
            if (r0 < M)
                *(float2*)&C[(size_t)r0 * Nc + c] = make_float2(acc[mt][nt].x, acc[mt][nt].y);
            if (r0 + 8 < M)
                *(float2*)&C[(size_t)(r0 + 8) * Nc + c] = make_float2(acc[mt][nt].z, acc[mt][nt].w);
        }
    }
}

// ---------------- CSR gather -------------------------------------------------
template <int H>
__global__ void k_gather(const float* __restrict__ hw, const float* __restrict__ dis,
                         const int* __restrict__ rowptr, const int* __restrict__ esrc,
                         float* __restrict__ agg, int N) {
    int warp = (blockIdx.x * blockDim.x + threadIdx.x) >> 5;
    int lane = threadIdx.x & 31;
    if (warp >= N) return;
    int d = warp;
    constexpr int V = H / 128;
    int c = lane * (H / 32);
    float4 acc[V];
#pragma unroll
    for (int v = 0; v < V; v++) acc[v] = make_float4(0.f, 0.f, 0.f, 0.f);
    int e0 = rowptr[d], e1 = rowptr[d + 1];
    for (int e = e0; e < e1; e++) {
        int s = esrc[e];
        float w = dis[s];
        const float* row = &hw[(size_t)s * H + c];
#pragma unroll
        for (int v = 0; v < V; v++) {
            float4 x = *(const float4*)&row[v * 4];
            acc[v].x += w * x.x; acc[v].y += w * x.y;
            acc[v].z += w * x.z; acc[v].w += w * x.w;
        }
    }
    float dd = dis[d];
    const float* self = &hw[(size_t)d * H + c];
    float* outp = &agg[(size_t)d * H + c];
#pragma unroll
    for (int v = 0; v < V; v++) {
        float4 x = *(const float4*)&self[v * 4];
        float4 r;
        r.x = dd * (acc[v].x + dd * x.x);
        r.y = dd * (acc[v].y + dd * x.y);
        r.z = dd * (acc[v].z + dd * x.z);
        r.w = dd * (acc[v].w + dd * x.w);
        *(float4*)&outp[v * 4] = r;
    }
}

// ---------------- BN stats ---------------------------------------------------
__global__ void k_stats(const float* __restrict__ agg, int N, int H) {
    int c = threadIdx.x;
    float s = 0.f, ss = 0.f;
    for (int r = blockIdx.x; r < N; r += gridDim.x) {
        float v = agg[(size_t)r * H + c];
        s += v; ss += v * v;
    }
    atomicAdd(&g_colsum[c], s);
    atomicAdd(&g_colsumsq[c], ss);
}
__global__ void k_zero_stats(int H) {
    int c = threadIdx.x;
    if (c < H) { g_colsum[c] = 0.f; g_colsumsq[c] = 0.f; }
}
__global__ void k_finalize_bn(const float* __restrict__ gam, const float* __restrict__ bet,
                              int N, int H) {
    int c = threadIdx.x;
    if (c >= H) return;
    float inv = 1.0f / (float)N;
    float mean = g_colsum[c] * inv;
    float var = fmaxf(g_colsumsq[c] * inv - mean * mean, 0.f);
    float sc = gam[c] * rsqrtf(var + BN_EPS);
    g_scale[c] = sc;
    g_shift[c] = bet[c] - mean * sc;
}

// ---------------- fp32 SGEMM (head only) with packed f32x2 -------------------
__device__ __forceinline__ unsigned long long dup_f32x2(float a) {
    unsigned long long r;
    unsigned int u = __float_as_uint(a);
    asm("mov.b64 %0, {%1, %1};" : "=l"(r) : "r"(u));
    return r;
}
__device__ __forceinline__ void fma2(unsigned long long& acc, unsigned long long a,
                                     unsigned long long b) {
    asm("fma.rn.f32x2 %0, %1, %2, %0;" : "+l"(acc) : "l"(a), "l"(b));
}
union F4U2 { float4 f; unsigned long long u[2]; };

template <bool BN, bool BIAS>
__global__ void __launch_bounds__(256)
k_sgemm(const float* __restrict__ A, const float* __restrict__ W,
        float* __restrict__ C, int M, int K, int Nc,
        const float* __restrict__ scale, const float* __restrict__ shift,
        const float* __restrict__ bias) {
    __shared__ float As[16][132];
    __shared__ float Ws[16][128];
    int tid = threadIdx.x;
    int tx = tid & 15;
    int ty = tid >> 4;
    int rowBase = blockIdx.y * 128;
    int colBase = blockIdx.x * 128;

    unsigned long long acc2[8][4];
#pragma unroll
    for (int i = 0; i < 8; i++)
#pragma unroll
        for (int j = 0; j < 4; j++) acc2[i][j] = 0ULL;

    for (int k0 = 0; k0 < K; k0 += 16) {
#pragma unroll
        for (int l = 0; l < 2; l++) {
            int lin = tid + l * 256;
            int ar = lin >> 2;
            int ac = (lin & 3) * 4;
            int r = rowBase + ar;
            float4 v = make_float4(0.f, 0.f, 0.f, 0.f);
            if (r < M) v = *(const float4*)&A[(size_t)r * K + k0 + ac];
            if (BN) {
                v.x = fmaxf(v.x * scale[k0 + ac + 0] + shift[k0 + ac + 0], 0.f);
                v.y = fmaxf(v.y * scale[k0 + ac + 1] + shift[k0 + ac + 1], 0.f);
                v.z = fmaxf(v.z * scale[k0 + ac + 2] + shift[k0 + ac + 2], 0.f);
                v.w = fmaxf(v.w * scale[k0 + ac + 3] + shift[k0 + ac + 3], 0.f);
            }
            As[ac + 0][ar] = v.x; As[ac + 1][ar] = v.y;
            As[ac + 2][ar] = v.z; As[ac + 3][ar] = v.w;
        }
#pragma unroll
        for (int l = 0; l < 2; l++) {
            int lin = tid + l * 256;
            int wr = lin >> 5;
            int wc = (lin & 31) * 4;
            *(float4*)&Ws[wr][wc] = *(const float4*)&W[(size_t)(k0 + wr) * Nc + colBase + wc];
        }
        __syncthreads();
#pragma unroll
        for (int k = 0; k < 16; k++) {
            F4U2 a0, a1, b0, b1;
            a0.f = *(float4*)&As[k][ty * 8];
            a1.f = *(float4*)&As[k][ty * 8 + 4];
            b0.f = *(float4*)&Ws[k][tx * 8];
            b1.f = *(float4*)&Ws[k][tx * 8 + 4];
            float av[8] = {a0.f.x, a0.f.y, a0.f.z, a0.f.w, a1.f.x, a1.f.y, a1.f.z, a1.f.w};
            unsigned long long bp[4] = {b0.u[0], b0.u[1], b1.u[0], b1.u[1]};
#pragma unroll
            for (int i = 0; i < 8; i++) {
                unsigned long long ad = dup_f32x2(av[i]);
#pragma unroll
                for (int jp = 0; jp < 4; jp++) fma2(acc2[i][jp], ad, bp[jp]);
            }
        }
        __syncthreads();
    }
#pragma unroll
    for (int i = 0; i < 8; i++) {
        int r = rowBase + ty * 8 + i;
        if (r >= M) continue;
#pragma unroll
        for (int jp = 0; jp < 4; jp += 2) {
            int c = colBase + tx * 8 + jp * 2;
            unsigned long long u0 = acc2[i][jp], u1 = acc2[i][jp + 1];
            float4 v;
            v.x = __uint_as_float((unsigned)u0);
            v.y = __uint_as_float((unsigned)(u0 >> 32));
            v.z = __uint_as_float((unsigned)u1);
            v.w = __uint_as_float((unsigned)(u1 >> 32));
            if (BIAS) { v.x += bias[c]; v.y += bias[c + 1]; v.z += bias[c + 2]; v.w += bias[c + 3]; }
            *(float4*)&C[(size_t)r * Nc + c] = v;
        }
    }
}

// ---------------- segmented pooling ------------------------------------------
__global__ void k_pool(const float* __restrict__ agg, const int* __restrict__ gptr,
                       float* __restrict__ pm) {
    int g = blockIdx.x;
    int c = threadIdx.x;
    int r0 = gptr[g], r1 = gptr[g + 1];
    float sc = g_scale[c], sh = g_shift[c];
    float s = 0.f;
    for (int r = r0; r < r1; r++) {
        float v = agg[(size_t)r * 256 + c];
        s += fmaxf(v * sc + sh, 0.f);
    }
    float cnt = (float)(r1 - r0);
    pm[(size_t)g * 256 + c] = s / fmaxf(cnt, 1.0f);
}

// ---------------- host driver ------------------------------------------------
static void exclusive_scan(int* data_in, int n, int* out, int* bsum, int* boff, int* dummy) {
    int nb = (n + 1023) / 1024;
    k_scan1<<<nb, 256>>>(data_in, n, out, bsum);
    k_scan1<<<1, 256>>>(bsum, nb, boff, dummy);
    k_scan_add<<<(n + 255) / 256, 256>>>(out, boff, n);
}

extern "C" void kernel_launch(void* const* d_in, const int* in_sizes, int n_in,
                              void* d_out, int out_size) {
    const float* x = (const float*)d_in[0];
    const int* ei = (const int*)d_in[1];
    const int* batch = (const int*)d_in[2];
    int o = (in_sizes[3] == 1) ? 4 : 3;
    const float* W1 = (const float*)d_in[o + 0];
    const float* gm1 = (const float*)d_in[o + 2];
    const float* be1 = (const float*)d_in[o + 3];
    const float* W2 = (const float*)d_in[o + 4];
    const float* gm2 = (const float*)d_in[o + 6];
    const float* be2 = (const float*)d_in[o + 7];
    const float* W3 = (const float*)d_in[o + 8];
    const float* gm3 = (const float*)d_in[o + 10];
    const float* be3 = (const float*)d_in[o + 11];
    const float* Wp = (const float*)d_in[o + 12];
    const float* bp = (const float*)d_in[o + 13];

    int N = in_sizes[0] / 9;
    int E = in_sizes[1] / 2;
    int P = in_sizes[o + 13];
    int G = out_size / P;

    float *dis, *hw, *agg, *pm, *scale, *shift;
    int *rowcnt, *rowptr, *fill, *esrc, *gcnt, *gptr, *bsum, *boff, *dummy;
    cudaGetSymbolAddress((void**)&dis, g_dis);
    cudaGetSymbolAddress((void**)&hw, g_hw);
    cudaGetSymbolAddress((void**)&agg, g_agg);
    cudaGetSymbolAddress((void**)&pm, g_pm);
    cudaGetSymbolAddress((void**)&scale, g_scale);
    cudaGetSymbolAddress((void**)&shift, g_shift);
    cudaGetSymbolAddress((void**)&rowcnt, g_rowcnt);
    cudaGetSymbolAddress((void**)&rowptr, g_rowptr);
    cudaGetSymbolAddress((void**)&fill, g_fill);
    cudaGetSymbolAddress((void**)&esrc, g_esrc);
    cudaGetSymbolAddress((void**)&gcnt, g_gcnt);
    cudaGetSymbolAddress((void**)&gptr, g_gptr);
    cudaGetSymbolAddress((void**)&bsum, g_bsum);
    cudaGetSymbolAddress((void**)&boff, g_boff);
    cudaGetSymbolAddress((void**)&dummy, g_dummy);

    const int* src = ei;
    const int* dst = ei + E;

    // ---- CSR build + norm ----
    k_zero_int<<<(N + 255) / 256, 256>>>(rowcnt, N);
    k_count<<<(E + 255) / 256, 256>>>(dst, rowcnt, E);
    k_dis<<<(N + 255) / 256, 256>>>(rowcnt, dis, N);
    exclusive_scan(rowcnt, N, rowptr, bsum, boff, dummy);
    k_set_int<<<1, 1>>>(rowptr + N, E);
    k_zero_int<<<(N + 255) / 256, 256>>>(fill, N);
    k_csr_fill<<<(E + 255) / 256, 256>>>(src, dst, rowptr, fill, esrc, E);

    // ---- graph segment ptrs (batch is sorted) ----
    k_zero_int<<<(G + 255) / 256, 256>>>(gcnt, G);
    k_count<<<(N + 255) / 256, 256>>>(batch, gcnt, N);
    exclusive_scan(gcnt, G, gptr, bsum, boff, dummy);
    k_set_int<<<1, 1>>>(gptr + G, N);

    // ---- layer 1 ----
    k_gemm1<<<(N + 7) / 8, 256>>>(x, W1, hw, N);
    k_gather<128><<<(N + 7) / 8, 256>>>(hw, dis, rowptr, esrc, agg, N);
    k_zero_stats<<<1, 128>>>(128);
    k_stats<<<1024, 128>>>(agg, N, 128);
    k_finalize_bn<<<1, 128>>>(gm1, be1, N, 128);

    // ---- layer 2 (tf32 mma.sync) ----
    {
        dim3 grid(2, (N + 127) / 128);
        k_gemm_mma<true><<<grid, 256>>>(agg, W2, hw, N, 128, 256, scale, shift);
    }
    k_gather<256><<<(N + 7) / 8, 256>>>(hw, dis, rowptr, esrc, agg, N);
    k_zero_stats<<<1, 256>>>(256);
    k_stats<<<1024, 256>>>(agg, N, 256);
    k_finalize_bn<<<1, 256>>>(gm2, be2, N, 256);

    // ---- layer 3 (tf32 mma.sync) ----
    {
        dim3 grid(2, (N + 127) / 128);
        k_gemm_mma<true><<<grid, 256>>>(agg, W3, hw, N, 256, 256, scale, shift);
    }
    k_gather<256><<<(N + 7) / 8, 256>>>(hw, dis, rowptr, esrc, agg, N);
    k_zero_stats<<<1, 256>>>(256);
    k_stats<<<1024, 256>>>(agg, N, 256);
    k_finalize_bn<<<1, 256>>>(gm3, be3, N, 256);

    // ---- pooling ----
    k_pool<<<G, 256>>>(agg, gptr, pm);

    // ---- head (fp32, keeps output precision) ----
    {
        dim3 grid(P / 128, (G + 127) / 128);
        k_sgemm<false, true><<<grid, 256>>>(pm, Wp, (float*)d_out, G, 256, P,
                                            nullptr, nullptr, bp);
    }
}

// round 9
// speedup vs baseline: 1.1938x; 1.0000x over previous
#include <cuda_runtime.h>
#include <stdint.h>

#define NMAX 200000
#define EMAX 400000
#define GMAX 8192
#define HMAX 256
#define BN_EPS 1e-5f

// ---------------- scratch (device globals: no allocation allowed) ----------
__device__ float g_dis[NMAX];
__device__ float g_hw[(size_t)NMAX * HMAX];
__device__ float g_agg[(size_t)NMAX * HMAX];
__device__ float g_colsum[HMAX];
__device__ float g_colsumsq[HMAX];
__device__ float g_scale[HMAX];
__device__ float g_shift[HMAX];
__device__ float g_pm[(size_t)GMAX * HMAX];
__device__ int g_rowcnt[NMAX];
__device__ int g_rowptr[NMAX + 1];
__device__ int g_fill[NMAX];
__device__ int g_esrc[EMAX];
__device__ int g_gcnt[GMAX];
__device__ int g_gptr[GMAX + 1];
__device__ int g_bsum[1024];
__device__ int g_boff[1024];
__device__ int g_dummy[4];

// ---------------- small utility kernels ------------------------------------
__global__ void k_zero_int(int* p, int n) {
    int i = blockIdx.x * blockDim.x + threadIdx.x;
    if (i < n) p[i] = 0;
}
__global__ void k_set_int(int* p, int v) { *p = v; }
__global__ void k_count(const int* __restrict__ idx, int* __restrict__ cnt, int n) {
    int i = blockIdx.x * blockDim.x + threadIdx.x;
    if (i < n) atomicAdd(&cnt[idx[i]], 1);
}
__global__ void k_dis(const int* __restrict__ cnt, float* __restrict__ dis, int n) {
    int i = blockIdx.x * blockDim.x + threadIdx.x;
    if (i < n) dis[i] = rsqrtf((float)cnt[i] + 1.0f);
}

// ---------------- 2-level exclusive scan (chunk = 1024) ---------------------
__global__ void k_scan1(const int* __restrict__ in, int n, int* __restrict__ out,
                        int* __restrict__ bsum) {
    __shared__ int sh[256];
    int t = threadIdx.x;
    int base = blockIdx.x * 1024 + t * 4;
    int v0 = (base + 0 < n) ? in[base + 0] : 0;
    int v1 = (base + 1 < n) ? in[base + 1] : 0;
    int v2 = (base + 2 < n) ? in[base + 2] : 0;
    int v3 = (base + 3 < n) ? in[base + 3] : 0;
    int s = v0 + v1 + v2 + v3;
    sh[t] = s;
    __syncthreads();
    for (int off = 1; off < 256; off <<= 1) {
        int x = (t >= off) ? sh[t - off] : 0;
        __syncthreads();
        sh[t] += x;
        __syncthreads();
    }
    int run = sh[t] - s;
    if (base + 0 < n) out[base + 0] = run; run += v0;
    if (base + 1 < n) out[base + 1] = run; run += v1;
    if (base + 2 < n) out[base + 2] = run; run += v2;
    if (base + 3 < n) out[base + 3] = run;
    if (t == 0) bsum[blockIdx.x] = sh[255];
}
__global__ void k_scan_add(int* __restrict__ out, const int* __restrict__ boff, int n) {
    int i = blockIdx.x * blockDim.x + threadIdx.x;
    if (i < n) out[i] += boff[i >> 10];
}

// ---------------- CSR fill ---------------------------------------------------
__global__ void k_csr_fill(const int* __restrict__ src, const int* __restrict__ dst,
                           const int* __restrict__ rowptr, int* __restrict__ fill,
                           int* __restrict__ esrc, int E) {
    int e = blockIdx.x * blockDim.x + threadIdx.x;
    if (e < E) {
        int d = dst[e];
        int pos = rowptr[d] + atomicAdd(&fill[d], 1);
        esrc[pos] = src[e];
    }
}

// ---------------- layer-1 GEMM: [N,9] @ [9,128] -----------------------------
__global__ void k_gemm1(const float* __restrict__ x, const float* __restrict__ W,
                        float* __restrict__ out, int N) {
    __shared__ float Ws[9 * 128];
    __shared__ float xs[8 * 9];
    int tid = threadIdx.x;
    for (int i = tid; i < 9 * 128; i += 256) Ws[i] = W[i];
    int r0 = blockIdx.x * 8;
    if (tid < 72) {
        int rr = tid / 9, cc = tid % 9;
        int r = r0 + rr;
        xs[tid] = (r < N) ? x[(size_t)r * 9 + cc] : 0.0f;
    }
    __syncthreads();
    int lr = tid >> 5;
    int c4 = (tid & 31) * 4;
    int r = r0 + lr;
    if (r >= N) return;
    float a0 = 0.f, a1 = 0.f, a2 = 0.f, a3 = 0.f;
#pragma unroll
    for (int k = 0; k < 9; k++) {
        float xv = xs[lr * 9 + k];
        const float* w = &Ws[k * 128 + c4];
        a0 += xv * w[0]; a1 += xv * w[1]; a2 += xv * w[2]; a3 += xv * w[3];
    }
    *(float4*)&out[(size_t)r * 128 + c4] = make_float4(a0, a1, a2, a3);
}

// ================= tf32 mma.sync GEMM (sm_80+ baseline ISA) =================
__device__ __forceinline__ uint32_t f2tf32(float x) {
    uint32_t u; asm("cvt.rna.tf32.f32 %0, %1;" : "=r"(u) : "f"(x)); return u;
}
__device__ __forceinline__ int swz(int k) { return ((k & 3) << 3) | (k >> 2); }

__device__ __forceinline__ void mma_tf32(float4& c, uint32_t a0, uint32_t a1,
                                         uint32_t a2, uint32_t a3,
                                         uint32_t b0, uint32_t b1) {
    asm volatile(
        "mma.sync.aligned.m16n8k8.row.col.f32.tf32.tf32.f32 "
        "{%0,%1,%2,%3}, {%4,%5,%6,%7}, {%8,%9}, {%0,%1,%2,%3};"
        : "+f"(c.x), "+f"(c.y), "+f"(c.z), "+f"(c.w)
        : "r"(a0), "r"(a1), "r"(a2), "r"(a3), "r"(b0), "r"(b1));
}

// C[M,Nc] = relu(BN(A[M,K])) @ W[K,Nc]; block tile 128x128, K-chunk 32.
// SMEM word layout: idx = k*128 + (m ^ swz(k))  (conflict-free frag LDS).
template <bool BN>
__global__ void __launch_bounds__(256, 1)
k_gemm_mma(const float* __restrict__ A, const float* __restrict__ W,
           float* __restrict__ C, int M, int K, int Nc,
           const float* __restrict__ scale, const float* __restrict__ shift) {
    __shared__ uint32_t As[32 * 128];
    __shared__ uint32_t Bs[32 * 128];
    int tid = threadIdx.x;
    int lane = tid & 31, warp = tid >> 5;
    int g = lane >> 2, tig = lane & 3;
    int wm = warp & 3, wn = warp >> 2;
    int rowBase = blockIdx.y * 128;
    int colBase = blockIdx.x * 128;

    float4 acc[2][8];
#pragma unroll
    for (int i = 0; i < 2; i++)
#pragma unroll
        for (int j = 0; j < 8; j++) acc[i][j] = make_float4(0.f, 0.f, 0.f, 0.f);

    for (int k0 = 0; k0 < K; k0 += 32) {
        // ---- A tile: 128 rows x 32 k (BN+ReLU fused), coalesced float4 ----
#pragma unroll
        for (int l = 0; l < 4; l++) {
            int lin = l * 256 + tid;
            int r = lin >> 3;
            int kq = (lin & 7) * 4;
            int gr = rowBase + r;
            float4 v = make_float4(0.f, 0.f, 0.f, 0.f);
            if (gr < M) v = *(const float4*)&A[(size_t)gr * K + k0 + kq];
            if (BN) {
                v.x = fmaxf(v.x * scale[k0 + kq + 0] + shift[k0 + kq + 0], 0.f);
                v.y = fmaxf(v.y * scale[k0 + kq + 1] + shift[k0 + kq + 1], 0.f);
                v.z = fmaxf(v.z * scale[k0 + kq + 2] + shift[k0 + kq + 2], 0.f);
                v.w = fmaxf(v.w * scale[k0 + kq + 3] + shift[k0 + kq + 3], 0.f);
            }
            As[(kq + 0) * 128 + (r ^ swz(kq + 0))] = f2tf32(v.x);
            As[(kq + 1) * 128 + (r ^ swz(kq + 1))] = f2tf32(v.y);
            As[(kq + 2) * 128 + (r ^ swz(kq + 2))] = f2tf32(v.z);
            As[(kq + 3) * 128 + (r ^ swz(kq + 3))] = f2tf32(v.w);
        }
        // ---- B tile: 32 k x 128 n, coalesced float4 along n ----
#pragma unroll
        for (int l = 0; l < 4; l++) {
            int lin = l * 256 + tid;
            int k = lin >> 5;
            int n4 = (lin & 31) * 4;
            float4 w4 = *(const float4*)&W[(size_t)(k0 + k) * Nc + colBase + n4];
            int xk = swz(k);
            Bs[k * 128 + ((n4 + 0) ^ xk)] = f2tf32(w4.x);
            Bs[k * 128 + ((n4 + 1) ^ xk)] = f2tf32(w4.y);
            Bs[k * 128 + ((n4 + 2) ^ xk)] = f2tf32(w4.z);
            Bs[k * 128 + ((n4 + 3) ^ xk)] = f2tf32(w4.w);
        }
        __syncthreads();
#pragma unroll
        for (int s = 0; s < 4; s++) {
            int kA = s * 8 + tig;
            int kB = kA + 4;
            int xa = swz(kA), xb = swz(kB);
            uint32_t a[2][4];
#pragma unroll
            for (int mt = 0; mt < 2; mt++) {
                int m = wm * 32 + mt * 16 + g;
                a[mt][0] = As[kA * 128 + (m ^ xa)];
                a[mt][1] = As[kA * 128 + ((m + 8) ^ xa)];
                a[mt][2] = As[kB * 128 + (m ^ xb)];
                a[mt][3] = As[kB * 128 + ((m + 8) ^ xb)];
            }
#pragma unroll
            for (int nt = 0; nt < 8; nt++) {
                int n = wn * 64 + nt * 8 + g;
                uint32_t b0 = Bs[kA * 128 + (n ^ xa)];
                uint32_t b1 = Bs[kB * 128 + (n ^ xb)];
                mma_tf32(acc[0][nt], a[0][0], a[0][1], a[0][2], a[0][3], b0, b1);
                mma_tf32(acc[1][nt], a[1][0], a[1][1], a[1][2], a[1][3], b0, b1);
            }
        }
        __syncthreads();
    }
    // ---- epilogue ----
#pragma unroll
    for (int mt = 0; mt < 2; mt++) {
        int r0 = rowBase + wm * 32 + mt * 16 + g;
#pragma unroll
        for (int nt = 0; nt < 8; nt++) {
            int c = colBase + wn * 64 + nt * 8 + tig * 2;
            if (r0 < M)
                *(float2*)&C[(size_t)r0 * Nc + c] = make_float2(acc[mt][nt].x, acc[mt][nt].y);
            if (r0 + 8 < M)
                *(float2*)&C[(size_t)(r0 + 8) * Nc + c] = make_float2(acc[mt][nt].z, acc[mt][nt].w);
        }
    }
}

// ---------------- CSR gather -------------------------------------------------
template <int H>
__global__ void k_gather(const float* __restrict__ hw, const float* __restrict__ dis,
                         const int* __restrict__ rowptr, const int* __restrict__ esrc,
                         float* __restrict__ agg, int N) {
    int warp = (blockIdx.x * blockDim.x + threadIdx.x) >> 5;
    int lane = threadIdx.x & 31;
    if (warp >= N) return;
    int d = warp;
    constexpr int V = H / 128;
    int c = lane * (H / 32);
    float4 acc[V];
#pragma unroll
    for (int v = 0; v < V; v++) acc[v] = make_float4(0.f, 0.f, 0.f, 0.f);
    int e0 = rowptr[d], e1 = rowptr[d + 1];
    for (int e = e0; e < e1; e++) {
        int s = esrc[e];
        float w = dis[s];
        const float* row = &hw[(size_t)s * H + c];
#pragma unroll
        for (int v = 0; v < V; v++) {
            float4 x = *(const float4*)&row[v * 4];
            acc[v].x += w * x.x; acc[v].y += w * x.y;
            acc[v].z += w * x.z; acc[v].w += w * x.w;
        }
    }
    float dd = dis[d];
    const float* self = &hw[(size_t)d * H + c];
    float* outp = &agg[(size_t)d * H + c];
#pragma unroll
    for (int v = 0; v < V; v++) {
        float4 x = *(const float4*)&self[v * 4];
        float4 r;
        r.x = dd * (acc[v].x + dd * x.x);
        r.y = dd * (acc[v].y + dd * x.y);
        r.z = dd * (acc[v].z + dd * x.z);
        r.w = dd * (acc[v].w + dd * x.w);
        *(float4*)&outp[v * 4] = r;
    }
}

// ---------------- BN stats ---------------------------------------------------
__global__ void k_stats(const float* __restrict__ agg, int N, int H) {
    int c = threadIdx.x;
    float s = 0.f, ss = 0.f;
    for (int r = blockIdx.x; r < N; r += gridDim.x) {
        float v = agg[(size_t)r * H + c];
        s += v; ss += v * v;
    }
    atomicAdd(&g_colsum[c], s);
    atomicAdd(&g_colsumsq[c], ss);
}
__global__ void k_zero_stats(int H) {
    int c = threadIdx.x;
    if (c < H) { g_colsum[c] = 0.f; g_colsumsq[c] = 0.f; }
}
__global__ void k_finalize_bn(const float* __restrict__ gam, const float* __restrict__ bet,
                              int N, int H) {
    int c = threadIdx.x;
    if (c >= H) return;
    float inv = 1.0f / (float)N;
    float mean = g_colsum[c] * inv;
    float var = fmaxf(g_colsumsq[c] * inv - mean * mean, 0.f);
    float sc = gam[c] * rsqrtf(var + BN_EPS);
    g_scale[c] = sc;
    g_shift[c] = bet[c] - mean * sc;
}

// ---------------- fp32 SGEMM (head only) with packed f32x2 -------------------
__device__ __forceinline__ unsigned long long dup_f32x2(float a) {
    unsigned long long r;
    unsigned int u = __float_as_uint(a);
    asm("mov.b64 %0, {%1, %1};" : "=l"(r) : "r"(u));
    return r;
}
__device__ __forceinline__ void fma2(unsigned long long& acc, unsigned long long a,
                                     unsigned long long b) {
    asm("fma.rn.f32x2 %0, %1, %2, %0;" : "+l"(acc) : "l"(a), "l"(b));
}
union F4U2 { float4 f; unsigned long long u[2]; };

template <bool BN, bool BIAS>
__global__ void __launch_bounds__(256)
k_sgemm(const float* __restrict__ A, const float* __restrict__ W,
        float* __restrict__ C, int M, int K, int Nc,
        const float* __restrict__ scale, const float* __restrict__ shift,
        const float* __restrict__ bias) {
    __shared__ float As[16][132];
    __shared__ float Ws[16][128];
    int tid = threadIdx.x;
    int tx = tid & 15;
    int ty = tid >> 4;
    int rowBase = blockIdx.y * 128;
    int colBase = blockIdx.x * 128;

    unsigned long long acc2[8][4];
#pragma unroll
    for (int i = 0; i < 8; i++)
#pragma unroll
        for (int j = 0; j < 4; j++) acc2[i][j] = 0ULL;

    for (int k0 = 0; k0 < K; k0 += 16) {
#pragma unroll
        for (int l = 0; l < 2; l++) {
            int lin = tid + l * 256;
            int ar = lin >> 2;
            int ac = (lin & 3) * 4;
            int r = rowBase + ar;
            float4 v = make_float4(0.f, 0.f, 0.f, 0.f);
            if (r < M) v = *(const float4*)&A[(size_t)r * K + k0 + ac];
            if (BN) {
                v.x = fmaxf(v.x * scale[k0 + ac + 0] + shift[k0 + ac + 0], 0.f);
                v.y = fmaxf(v.y * scale[k0 + ac + 1] + shift[k0 + ac + 1], 0.f);
                v.z = fmaxf(v.z * scale[k0 + ac + 2] + shift[k0 + ac + 2], 0.f);
                v.w = fmaxf(v.w * scale[k0 + ac + 3] + shift[k0 + ac + 3], 0.f);
            }
            As[ac + 0][ar] = v.x; As[ac + 1][ar] = v.y;
            As[ac + 2][ar] = v.z; As[ac + 3][ar] = v.w;
        }
#pragma unroll
        for (int l = 0; l < 2; l++) {
            int lin = tid + l * 256;
            int wr = lin >> 5;
            int wc = (lin & 31) * 4;
            *(float4*)&Ws[wr][wc] = *(const float4*)&W[(size_t)(k0 + wr) * Nc + colBase + wc];
        }
        __syncthreads();
#pragma unroll
        for (int k = 0; k < 16; k++) {
            F4U2 a0, a1, b0, b1;
            a0.f = *(float4*)&As[k][ty * 8];
            a1.f = *(float4*)&As[k][ty * 8 + 4];
            b0.f = *(float4*)&Ws[k][tx * 8];
            b1.f = *(float4*)&Ws[k][tx * 8 + 4];
            float av[8] = {a0.f.x, a0.f.y, a0.f.z, a0.f.w, a1.f.x, a1.f.y, a1.f.z, a1.f.w};
            unsigned long long bp[4] = {b0.u[0], b0.u[1], b1.u[0], b1.u[1]};
#pragma unroll
            for (int i = 0; i < 8; i++) {
                unsigned long long ad = dup_f32x2(av[i]);
#pragma unroll
                for (int jp = 0; jp < 4; jp++) fma2(acc2[i][jp], ad, bp[jp]);
            }
        }
        __syncthreads();
    }
#pragma unroll
    for (int i = 0; i < 8; i++) {
        int r = rowBase + ty * 8 + i;
        if (r >= M) continue;
#pragma unroll
        for (int jp = 0; jp < 4; jp += 2) {
            int c = colBase + tx * 8 + jp * 2;
            unsigned long long u0 = acc2[i][jp], u1 = acc2[i][jp + 1];
            float4 v;
            v.x = __uint_as_float((unsigned)u0);
            v.y = __uint_as_float((unsigned)(u0 >> 32));
            v.z = __uint_as_float((unsigned)u1);
            v.w = __uint_as_float((unsigned)(u1 >> 32));
            if (BIAS) { v.x += bias[c]; v.y += bias[c + 1]; v.z += bias[c + 2]; v.w += bias[c + 3]; }
            *(float4*)&C[(size_t)r * Nc + c] = v;
        }
    }
}

// ---------------- segmented pooling ------------------------------------------
__global__ void k_pool(const float* __restrict__ agg, const int* __restrict__ gptr,
                       float* __restrict__ pm) {
    int g = blockIdx.x;
    int c = threadIdx.x;
    int r0 = gptr[g], r1 = gptr[g + 1];
    float sc = g_scale[c], sh = g_shift[c];
    float s = 0.f;
    for (int r = r0; r < r1; r++) {
        float v = agg[(size_t)r * 256 + c];
        s += fmaxf(v * sc + sh, 0.f);
    }
    float cnt = (float)(r1 - r0);
    pm[(size_t)g * 256 + c] = s / fmaxf(cnt, 1.0f);
}

// ---------------- host driver ------------------------------------------------
static void exclusive_scan(int* data_in, int n, int* out, int* bsum, int* boff, int* dummy) {
    int nb = (n + 1023) / 1024;
    k_scan1<<<nb, 256>>>(data_in, n, out, bsum);
    k_scan1<<<1, 256>>>(bsum, nb, boff, dummy);
    k_scan_add<<<(n + 255) / 256, 256>>>(out, boff, n);
}

extern "C" void kernel_launch(void* const* d_in, const int* in_sizes, int n_in,
                              void* d_out, int out_size) {
    const float* x = (const float*)d_in[0];
    const int* ei = (const int*)d_in[1];
    const int* batch = (const int*)d_in[2];
    int o = (in_sizes[3] == 1) ? 4 : 3;
    const float* W1 = (const float*)d_in[o + 0];
    const float* gm1 = (const float*)d_in[o + 2];
    const float* be1 = (const float*)d_in[o + 3];
    const float* W2 = (const float*)d_in[o + 4];
    const float* gm2 = (const float*)d_in[o + 6];
    const float* be2 = (const float*)d_in[o + 7];
    const float* W3 = (const float*)d_in[o + 8];
    const float* gm3 = (const float*)d_in[o + 10];
    const float* be3 = (const float*)d_in[o + 11];
    const float* Wp = (const float*)d_in[o + 12];
    const float* bp = (const float*)d_in[o + 13];

    int N = in_sizes[0] / 9;
    int E = in_sizes[1] / 2;
    int P = in_sizes[o + 13];
    int G = out_size / P;

    float *dis, *hw, *agg, *pm, *scale, *shift;
    int *rowcnt, *rowptr, *fill, *esrc, *gcnt, *gptr, *bsum, *boff, *dummy;
    cudaGetSymbolAddress((void**)&dis, g_dis);
    cudaGetSymbolAddress((void**)&hw, g_hw);
    cudaGetSymbolAddress((void**)&agg, g_agg);
    cudaGetSymbolAddress((void**)&pm, g_pm);
    cudaGetSymbolAddress((void**)&scale, g_scale);
    cudaGetSymbolAddress((void**)&shift, g_shift);
    cudaGetSymbolAddress((void**)&rowcnt, g_rowcnt);
    cudaGetSymbolAddress((void**)&rowptr, g_rowptr);
    cudaGetSymbolAddress((void**)&fill, g_fill);
    cudaGetSymbolAddress((void**)&esrc, g_esrc);
    cudaGetSymbolAddress((void**)&gcnt, g_gcnt);
    cudaGetSymbolAddress((void**)&gptr, g_gptr);
    cudaGetSymbolAddress((void**)&bsum, g_bsum);
    cudaGetSymbolAddress((void**)&boff, g_boff);
    cudaGetSymbolAddress((void**)&dummy, g_dummy);

    const int* src = ei;
    const int* dst = ei + E;

    // ---- CSR build + norm ----
    k_zero_int<<<(N + 255) / 256, 256>>>(rowcnt, N);
    k_count<<<(E + 255) / 256, 256>>>(dst, rowcnt, E);
    k_dis<<<(N + 255) / 256, 256>>>(rowcnt, dis, N);
    exclusive_scan(rowcnt, N, rowptr, bsum, boff, dummy);
    k_set_int<<<1, 1>>>(rowptr + N, E);
    k_zero_int<<<(N + 255) / 256, 256>>>(fill, N);
    k_csr_fill<<<(E + 255) / 256, 256>>>(src, dst, rowptr, fill, esrc, E);

    // ---- graph segment ptrs (batch is sorted) ----
    k_zero_int<<<(G + 255) / 256, 256>>>(gcnt, G);
    k_count<<<(N + 255) / 256, 256>>>(batch, gcnt, N);
    exclusive_scan(gcnt, G, gptr, bsum, boff, dummy);
    k_set_int<<<1, 1>>>(gptr + G, N);

    // ---- layer 1 ----
    k_gemm1<<<(N + 7) / 8, 256>>>(x, W1, hw, N);
    k_gather<128><<<(N + 7) / 8, 256>>>(hw, dis, rowptr, esrc, agg, N);
    k_zero_stats<<<1, 128>>>(128);
    k_stats<<<1024, 128>>>(agg, N, 128);
    k_finalize_bn<<<1, 128>>>(gm1, be1, N, 128);

    // ---- layer 2 (tf32 mma.sync) ----
    {
        dim3 grid(2, (N + 127) / 128);
        k_gemm_mma<true><<<grid, 256>>>(agg, W2, hw, N, 128, 256, scale, shift);
    }
    k_gather<256><<<(N + 7) / 8, 256>>>(hw, dis, rowptr, esrc, agg, N);
    k_zero_stats<<<1, 256>>>(256);
    k_stats<<<1024, 256>>>(agg, N, 256);
    k_finalize_bn<<<1, 256>>>(gm2, be2, N, 256);

    // ---- layer 3 (tf32 mma.sync) ----
    {
        dim3 grid(2, (N + 127) / 128);
        k_gemm_mma<true><<<grid, 256>>>(agg, W3, hw, N, 256, 256, scale, shift);
    }
    k_gather<256><<<(N + 7) / 8, 256>>>(hw, dis, rowptr, esrc, agg, N);
    k_zero_stats<<<1, 256>>>(256);
    k_stats<<<1024, 256>>>(agg, N, 256);
    k_finalize_bn<<<1, 256>>>(gm3, be3, N, 256);

    // ---- pooling ----
    k_pool<<<G, 256>>>(agg, gptr, pm);

    // ---- head (fp32, keeps output precision) ----
    {
        dim3 grid(P / 128, (G + 127) / 128);
        k_sgemm<false, true><<<grid, 256>>>(pm, Wp, (float*)d_out, G, 256, P,
                                            nullptr, nullptr, bp);
    }
}

// round 10
// speedup vs baseline: 1.4905x; 1.2486x over previous
#include <cuda_runtime.h>
#include <stdint.h>

#define NMAX 200000
#define EMAX 400000
#define GMAX 8192
#define HMAX 256
#define BN_EPS 1e-5f

// ---------------- scratch (device globals: no allocation allowed) ----------
__device__ float g_dis[NMAX];
__device__ float g_hw[(size_t)NMAX * HMAX];    // z = (Âh) @ W  (GEMM outputs)
__device__ float g_agg[(size_t)NMAX * HMAX];   // a = Â h      (gather outputs)
__device__ float g_colsum[HMAX];
__device__ float g_colsumsq[HMAX];
__device__ float g_scale[HMAX];
__device__ float g_shift[HMAX];
__device__ float g_pm[(size_t)GMAX * HMAX];
__device__ int g_rowcnt[NMAX];
__device__ int g_rowptr[NMAX + 1];
__device__ int g_fill[NMAX];
__device__ int g_esrc[EMAX];
__device__ int g_gcnt[GMAX];
__device__ int g_gptr[GMAX + 1];
__device__ int g_bsum[1024];
__device__ int g_boff[1024];
__device__ int g_dummy[4];

// ---------------- small utility kernels ------------------------------------
__global__ void k_zero_int(int* p, int n) {
    int i = blockIdx.x * blockDim.x + threadIdx.x;
    if (i < n) p[i] = 0;
}
__global__ void k_set_int(int* p, int v) { *p = v; }
__global__ void k_count(const int* __restrict__ idx, int* __restrict__ cnt, int n) {
    int i = blockIdx.x * blockDim.x + threadIdx.x;
    if (i < n) atomicAdd(&cnt[idx[i]], 1);
}
__global__ void k_dis(const int* __restrict__ cnt, float* __restrict__ dis, int n) {
    int i = blockIdx.x * blockDim.x + threadIdx.x;
    if (i < n) dis[i] = rsqrtf((float)cnt[i] + 1.0f);
}

// ---------------- 2-level exclusive scan (chunk = 1024) ---------------------
__global__ void k_scan1(const int* __restrict__ in, int n, int* __restrict__ out,
                        int* __restrict__ bsum) {
    __shared__ int sh[256];
    int t = threadIdx.x;
    int base = blockIdx.x * 1024 + t * 4;
    int v0 = (base + 0 < n) ? in[base + 0] : 0;
    int v1 = (base + 1 < n) ? in[base + 1] : 0;
    int v2 = (base + 2 < n) ? in[base + 2] : 0;
    int v3 = (base + 3 < n) ? in[base + 3] : 0;
    int s = v0 + v1 + v2 + v3;
    sh[t] = s;
    __syncthreads();
    for (int off = 1; off < 256; off <<= 1) {
        int x = (t >= off) ? sh[t - off] : 0;
        __syncthreads();
        sh[t] += x;
        __syncthreads();
    }
    int run = sh[t] - s;
    if (base + 0 < n) out[base + 0] = run; run += v0;
    if (base + 1 < n) out[base + 1] = run; run += v1;
    if (base + 2 < n) out[base + 2] = run; run += v2;
    if (base + 3 < n) out[base + 3] = run;
    if (t == 0) bsum[blockIdx.x] = sh[255];
}
__global__ void k_scan_add(int* __restrict__ out, const int* __restrict__ boff, int n) {
    int i = blockIdx.x * blockDim.x + threadIdx.x;
    if (i < n) out[i] += boff[i >> 10];
}

// ---------------- CSR fill ---------------------------------------------------
__global__ void k_csr_fill(const int* __restrict__ src, const int* __restrict__ dst,
                           const int* __restrict__ rowptr, int* __restrict__ fill,
                           int* __restrict__ esrc, int E) {
    int e = blockIdx.x * blockDim.x + threadIdx.x;
    if (e < E) {
        int d = dst[e];
        int pos = rowptr[d] + atomicAdd(&fill[d], 1);
        esrc[pos] = src[e];
    }
}

// ---------------- width-9 gather: a0 = Â x ----------------------------------
__global__ void k_gather9(const float* __restrict__ x, const float* __restrict__ dis,
                          const int* __restrict__ rowptr, const int* __restrict__ esrc,
                          float* __restrict__ out, int N) {
    int n = blockIdx.x * blockDim.x + threadIdx.x;
    if (n >= N) return;
    float dd = dis[n];
    float a[9];
#pragma unroll
    for (int f = 0; f < 9; f++) a[f] = dd * x[(size_t)n * 9 + f];
    int e0 = rowptr[n], e1 = rowptr[n + 1];
    for (int e = e0; e < e1; e++) {
        int s = esrc[e];
        float w = dis[s];
#pragma unroll
        for (int f = 0; f < 9; f++) a[f] += w * x[(size_t)s * 9 + f];
    }
#pragma unroll
    for (int f = 0; f < 9; f++) out[(size_t)n * 9 + f] = dd * a[f];
}

// ---------------- layer-1 GEMM: [N,9] @ [9,128] -----------------------------
__global__ void k_gemm1(const float* __restrict__ x, const float* __restrict__ W,
                        float* __restrict__ out, int N) {
    __shared__ float Ws[9 * 128];
    __shared__ float xs[8 * 9];
    int tid = threadIdx.x;
    for (int i = tid; i < 9 * 128; i += 256) Ws[i] = W[i];
    int r0 = blockIdx.x * 8;
    if (tid < 72) {
        int rr = tid / 9, cc = tid % 9;
        int r = r0 + rr;
        xs[tid] = (r < N) ? x[(size_t)r * 9 + cc] : 0.0f;
    }
    __syncthreads();
    int lr = tid >> 5;
    int c4 = (tid & 31) * 4;
    int r = r0 + lr;
    if (r >= N) return;
    float a0 = 0.f, a1 = 0.f, a2 = 0.f, a3 = 0.f;
#pragma unroll
    for (int k = 0; k < 9; k++) {
        float xv = xs[lr * 9 + k];
        const float* w = &Ws[k * 128 + c4];
        a0 += xv * w[0]; a1 += xv * w[1]; a2 += xv * w[2]; a3 += xv * w[3];
    }
    *(float4*)&out[(size_t)r * 128 + c4] = make_float4(a0, a1, a2, a3);
}

// ================= tf32 mma.sync GEMM + fused column stats ==================
__device__ __forceinline__ uint32_t f2tf32(float x) {
    uint32_t u; asm("cvt.rna.tf32.f32 %0, %1;" : "=r"(u) : "f"(x)); return u;
}
__device__ __forceinline__ int swz(int k) { return ((k & 3) << 3) | (k >> 2); }

__device__ __forceinline__ void mma_tf32(float4& c, uint32_t a0, uint32_t a1,
                                         uint32_t a2, uint32_t a3,
                                         uint32_t b0, uint32_t b1) {
    asm volatile(
        "mma.sync.aligned.m16n8k8.row.col.f32.tf32.tf32.f32 "
        "{%0,%1,%2,%3}, {%4,%5,%6,%7}, {%8,%9}, {%0,%1,%2,%3};"
        : "+f"(c.x), "+f"(c.y), "+f"(c.z), "+f"(c.w)
        : "r"(a0), "r"(a1), "r"(a2), "r"(a3), "r"(b0), "r"(b1));
}

// C[M,Nc] = A[M,K] @ W[K,Nc]; block tile 128x128, K-chunk 32.
// STATS: accumulate per-column sum / sumsq into g_colsum / g_colsumsq.
template <bool STATS>
__global__ void __launch_bounds__(256, 1)
k_gemm_mma(const float* __restrict__ A, const float* __restrict__ W,
           float* __restrict__ C, int M, int K, int Nc) {
    __shared__ uint32_t As[32 * 128];
    __shared__ uint32_t Bs[32 * 128];
    int tid = threadIdx.x;
    int lane = tid & 31, warp = tid >> 5;
    int g = lane >> 2, tig = lane & 3;
    int wm = warp & 3, wn = warp >> 2;
    int rowBase = blockIdx.y * 128;
    int colBase = blockIdx.x * 128;

    float4 acc[2][8];
#pragma unroll
    for (int i = 0; i < 2; i++)
#pragma unroll
        for (int j = 0; j < 8; j++) acc[i][j] = make_float4(0.f, 0.f, 0.f, 0.f);

    for (int k0 = 0; k0 < K; k0 += 32) {
#pragma unroll
        for (int l = 0; l < 4; l++) {
            int lin = l * 256 + tid;
            int r = lin >> 3;
            int kq = (lin & 7) * 4;
            int gr = rowBase + r;
            float4 v = make_float4(0.f, 0.f, 0.f, 0.f);
            if (gr < M) v = *(const float4*)&A[(size_t)gr * K + k0 + kq];
            As[(kq + 0) * 128 + (r ^ swz(kq + 0))] = f2tf32(v.x);
            As[(kq + 1) * 128 + (r ^ swz(kq + 1))] = f2tf32(v.y);
            As[(kq + 2) * 128 + (r ^ swz(kq + 2))] = f2tf32(v.z);
            As[(kq + 3) * 128 + (r ^ swz(kq + 3))] = f2tf32(v.w);
        }
#pragma unroll
        for (int l = 0; l < 4; l++) {
            int lin = l * 256 + tid;
            int k = lin >> 5;
            int n4 = (lin & 31) * 4;
            float4 w4 = *(const float4*)&W[(size_t)(k0 + k) * Nc + colBase + n4];
            int xk = swz(k);
            Bs[k * 128 + ((n4 + 0) ^ xk)] = f2tf32(w4.x);
            Bs[k * 128 + ((n4 + 1) ^ xk)] = f2tf32(w4.y);
            Bs[k * 128 + ((n4 + 2) ^ xk)] = f2tf32(w4.z);
            Bs[k * 128 + ((n4 + 3) ^ xk)] = f2tf32(w4.w);
        }
        __syncthreads();
#pragma unroll
        for (int s = 0; s < 4; s++) {
            int kA = s * 8 + tig;
            int kB = kA + 4;
            int xa = swz(kA), xb = swz(kB);
            uint32_t a[2][4];
#pragma unroll
            for (int mt = 0; mt < 2; mt++) {
                int m = wm * 32 + mt * 16 + g;
                a[mt][0] = As[kA * 128 + (m ^ xa)];
                a[mt][1] = As[kA * 128 + ((m + 8) ^ xa)];
                a[mt][2] = As[kB * 128 + (m ^ xb)];
                a[mt][3] = As[kB * 128 + ((m + 8) ^ xb)];
            }
#pragma unroll
            for (int nt = 0; nt < 8; nt++) {
                int n = wn * 64 + nt * 8 + g;
                uint32_t b0 = Bs[kA * 128 + (n ^ xa)];
                uint32_t b1 = Bs[kB * 128 + (n ^ xb)];
                mma_tf32(acc[0][nt], a[0][0], a[0][1], a[0][2], a[0][3], b0, b1);
                mma_tf32(acc[1][nt], a[1][0], a[1][1], a[1][2], a[1][3], b0, b1);
            }
        }
        __syncthreads();
    }
    // ---- store ----
#pragma unroll
    for (int mt = 0; mt < 2; mt++) {
        int r0 = rowBase + wm * 32 + mt * 16 + g;
#pragma unroll
        for (int nt = 0; nt < 8; nt++) {
            int c = colBase + wn * 64 + nt * 8 + tig * 2;
            if (r0 < M)
                *(float2*)&C[(size_t)r0 * Nc + c] = make_float2(acc[mt][nt].x, acc[mt][nt].y);
            if (r0 + 8 < M)
                *(float2*)&C[(size_t)(r0 + 8) * Nc + c] = make_float2(acc[mt][nt].z, acc[mt][nt].w);
        }
    }
    // ---- fused BN stats: butterfly over the 8 row-groups, atomics from 4 lanes
    if (STATS) {
#pragma unroll
        for (int nt = 0; nt < 8; nt++) {
            float4 u = acc[0][nt], v = acc[1][nt];
            float s0 = u.x + u.z + v.x + v.z;
            float s1 = u.y + u.w + v.y + v.w;
            float q0 = u.x * u.x + u.z * u.z + v.x * v.x + v.z * v.z;
            float q1 = u.y * u.y + u.w * u.w + v.y * v.y + v.w * v.w;
#pragma unroll
            for (int off = 4; off < 32; off <<= 1) {
                s0 += __shfl_xor_sync(0xffffffffu, s0, off);
                s1 += __shfl_xor_sync(0xffffffffu, s1, off);
                q0 += __shfl_xor_sync(0xffffffffu, q0, off);
                q1 += __shfl_xor_sync(0xffffffffu, q1, off);
            }
            if (lane < 4) {
                int c = colBase + wn * 64 + nt * 8 + lane * 2;
                atomicAdd(&g_colsum[c], s0);
                atomicAdd(&g_colsum[c + 1], s1);
                atomicAdd(&g_colsumsq[c], q0);
                atomicAdd(&g_colsumsq[c + 1], q1);
            }
        }
    }
}

// ---------------- CSR gather (optionally BN+ReLU on source rows) ------------
template <int H, bool BN>
__global__ void k_gather(const float* __restrict__ hw, const float* __restrict__ dis,
                         const int* __restrict__ rowptr, const int* __restrict__ esrc,
                         float* __restrict__ agg, int N) {
    int warp = (blockIdx.x * blockDim.x + threadIdx.x) >> 5;
    int lane = threadIdx.x & 31;
    if (warp >= N) return;
    int d = warp;
    constexpr int V = H / 128;
    int c = lane * (H / 32);
    float4 sc[V], sh[V];
    if (BN) {
#pragma unroll
        for (int v = 0; v < V; v++) {
            sc[v] = *(const float4*)&g_scale[c + v * 4];
            sh[v] = *(const float4*)&g_shift[c + v * 4];
        }
    }
    float4 acc[V];
#pragma unroll
    for (int v = 0; v < V; v++) acc[v] = make_float4(0.f, 0.f, 0.f, 0.f);
    int e0 = rowptr[d], e1 = rowptr[d + 1];
    for (int e = e0; e < e1; e++) {
        int s = esrc[e];
        float w = dis[s];
        const float* row = &hw[(size_t)s * H + c];
#pragma unroll
        for (int v = 0; v < V; v++) {
            float4 x = *(const float4*)&row[v * 4];
            if (BN) {
                x.x = fmaxf(x.x * sc[v].x + sh[v].x, 0.f);
                x.y = fmaxf(x.y * sc[v].y + sh[v].y, 0.f);
                x.z = fmaxf(x.z * sc[v].z + sh[v].z, 0.f);
                x.w = fmaxf(x.w * sc[v].w + sh[v].w, 0.f);
            }
            acc[v].x += w * x.x; acc[v].y += w * x.y;
            acc[v].z += w * x.z; acc[v].w += w * x.w;
        }
    }
    float dd = dis[d];
    const float* self = &hw[(size_t)d * H + c];
    float* outp = &agg[(size_t)d * H + c];
#pragma unroll
    for (int v = 0; v < V; v++) {
        float4 x = *(const float4*)&self[v * 4];
        if (BN) {
            x.x = fmaxf(x.x * sc[v].x + sh[v].x, 0.f);
            x.y = fmaxf(x.y * sc[v].y + sh[v].y, 0.f);
            x.z = fmaxf(x.z * sc[v].z + sh[v].z, 0.f);
            x.w = fmaxf(x.w * sc[v].w + sh[v].w, 0.f);
        }
        float4 r;
        r.x = dd * (acc[v].x + dd * x.x);
        r.y = dd * (acc[v].y + dd * x.y);
        r.z = dd * (acc[v].z + dd * x.z);
        r.w = dd * (acc[v].w + dd * x.w);
        *(float4*)&outp[v * 4] = r;
    }
}

// ---------------- BN stats (layer-1 only) ------------------------------------
__global__ void k_stats(const float* __restrict__ agg, int N, int H) {
    int c = threadIdx.x;
    float s = 0.f, ss = 0.f;
    for (int r = blockIdx.x; r < N; r += gridDim.x) {
        float v = agg[(size_t)r * H + c];
        s += v; ss += v * v;
    }
    atomicAdd(&g_colsum[c], s);
    atomicAdd(&g_colsumsq[c], ss);
}
__global__ void k_zero_stats(int H) {
    int c = threadIdx.x;
    if (c < H) { g_colsum[c] = 0.f; g_colsumsq[c] = 0.f; }
}
__global__ void k_finalize_bn(const float* __restrict__ gam, const float* __restrict__ bet,
                              int N, int H) {
    int c = threadIdx.x;
    if (c >= H) return;
    float inv = 1.0f / (float)N;
    float mean = g_colsum[c] * inv;
    float var = fmaxf(g_colsumsq[c] * inv - mean * mean, 0.f);
    float sc = gam[c] * rsqrtf(var + BN_EPS);
    g_scale[c] = sc;
    g_shift[c] = bet[c] - mean * sc;
}

// ---------------- fp32 SGEMM (head only) with packed f32x2 -------------------
__device__ __forceinline__ unsigned long long dup_f32x2(float a) {
    unsigned long long r;
    unsigned int u = __float_as_uint(a);
    asm("mov.b64 %0, {%1, %1};" : "=l"(r) : "r"(u));
    return r;
}
__device__ __forceinline__ void fma2(unsigned long long& acc, unsigned long long a,
                                     unsigned long long b) {
    asm("fma.rn.f32x2 %0, %1, %2, %0;" : "+l"(acc) : "l"(a), "l"(b));
}
union F4U2 { float4 f; unsigned long long u[2]; };

template <bool BIAS>
__global__ void __launch_bounds__(256)
k_sgemm(const float* __restrict__ A, const float* __restrict__ W,
        float* __restrict__ C, int M, int K, int Nc,
        const float* __restrict__ bias) {
    __shared__ float As[16][132];
    __shared__ float Ws[16][128];
    int tid = threadIdx.x;
    int tx = tid & 15;
    int ty = tid >> 4;
    int rowBase = blockIdx.y * 128;
    int colBase = blockIdx.x * 128;

    unsigned long long acc2[8][4];
#pragma unroll
    for (int i = 0; i < 8; i++)
#pragma unroll
        for (int j = 0; j < 4; j++) acc2[i][j] = 0ULL;

    for (int k0 = 0; k0 < K; k0 += 16) {
#pragma unroll
        for (int l = 0; l < 2; l++) {
            int lin = tid + l * 256;
            int ar = lin >> 2;
            int ac = (lin & 3) * 4;
            int r = rowBase + ar;
            float4 v = make_float4(0.f, 0.f, 0.f, 0.f);
            if (r < M) v = *(const float4*)&A[(size_t)r * K + k0 + ac];
            As[ac + 0][ar] = v.x; As[ac + 1][ar] = v.y;
            As[ac + 2][ar] = v.z; As[ac + 3][ar] = v.w;
        }
#pragma unroll
        for (int l = 0; l < 2; l++) {
            int lin = tid + l * 256;
            int wr = lin >> 5;
            int wc = (lin & 31) * 4;
            *(float4*)&Ws[wr][wc] = *(const float4*)&W[(size_t)(k0 + wr) * Nc + colBase + wc];
        }
        __syncthreads();
#pragma unroll
        for (int k = 0; k < 16; k++) {
            F4U2 a0, a1, b0, b1;
            a0.f = *(float4*)&As[k][ty * 8];
            a1.f = *(float4*)&As[k][ty * 8 + 4];
            b0.f = *(float4*)&Ws[k][tx * 8];
            b1.f = *(float4*)&Ws[k][tx * 8 + 4];
            float av[8] = {a0.f.x, a0.f.y, a0.f.z, a0.f.w, a1.f.x, a1.f.y, a1.f.z, a1.f.w};
            unsigned long long bp[4] = {b0.u[0], b0.u[1], b1.u[0], b1.u[1]};
#pragma unroll
            for (int i = 0; i < 8; i++) {
                unsigned long long ad = dup_f32x2(av[i]);
#pragma unroll
                for (int jp = 0; jp < 4; jp++) fma2(acc2[i][jp], ad, bp[jp]);
            }
        }
        __syncthreads();
    }
#pragma unroll
    for (int i = 0; i < 8; i++) {
        int r = rowBase + ty * 8 + i;
        if (r >= M) continue;
#pragma unroll
        for (int jp = 0; jp < 4; jp += 2) {
            int c = colBase + tx * 8 + jp * 2;
            unsigned long long u0 = acc2[i][jp], u1 = acc2[i][jp + 1];
            float4 v;
            v.x = __uint_as_float((unsigned)u0);
            v.y = __uint_as_float((unsigned)(u0 >> 32));
            v.z = __uint_as_float((unsigned)u1);
            v.w = __uint_as_float((unsigned)(u1 >> 32));
            if (BIAS) { v.x += bias[c]; v.y += bias[c + 1]; v.z += bias[c + 2]; v.w += bias[c + 3]; }
            *(float4*)&C[(size_t)r * Nc + c] = v;
        }
    }
}

// ---------------- segmented pooling (BN3+ReLU fused) --------------------------
__global__ void k_pool(const float* __restrict__ agg, const int* __restrict__ gptr,
                       float* __restrict__ pm) {
    int g = blockIdx.x;
    int c = threadIdx.x;
    int r0 = gptr[g], r1 = gptr[g + 1];
    float sc = g_scale[c], sh = g_shift[c];
    float s = 0.f;
    for (int r = r0; r < r1; r++) {
        float v = agg[(size_t)r * 256 + c];
        s += fmaxf(v * sc + sh, 0.f);
    }
    float cnt = (float)(r1 - r0);
    pm[(size_t)g * 256 + c] = s / fmaxf(cnt, 1.0f);
}

// ---------------- host driver ------------------------------------------------
static void exclusive_scan(int* data_in, int n, int* out, int* bsum, int* boff, int* dummy) {
    int nb = (n + 1023) / 1024;
    k_scan1<<<nb, 256>>>(data_in, n, out, bsum);
    k_scan1<<<1, 256>>>(bsum, nb, boff, dummy);
    k_scan_add<<<(n + 255) / 256, 256>>>(out, boff, n);
}

extern "C" void kernel_launch(void* const* d_in, const int* in_sizes, int n_in,
                              void* d_out, int out_size) {
    const float* x = (const float*)d_in[0];
    const int* ei = (const int*)d_in[1];
    const int* batch = (const int*)d_in[2];
    int o = (in_sizes[3] == 1) ? 4 : 3;
    const float* W1 = (const float*)d_in[o + 0];
    const float* gm1 = (const float*)d_in[o + 2];
    const float* be1 = (const float*)d_in[o + 3];
    const float* W2 = (const float*)d_in[o + 4];
    const float* gm2 = (const float*)d_in[o + 6];
    const float* be2 = (const float*)d_in[o + 7];
    const float* W3 = (const float*)d_in[o + 8];
    const float* gm3 = (const float*)d_in[o + 10];
    const float* be3 = (const float*)d_in[o + 11];
    const float* Wp = (const float*)d_in[o + 12];
    const float* bp = (const float*)d_in[o + 13];

    int N = in_sizes[0] / 9;
    int E = in_sizes[1] / 2;
    int P = in_sizes[o + 13];
    int G = out_size / P;

    float *dis, *hw, *agg, *pm;
    int *rowcnt, *rowptr, *fill, *esrc, *gcnt, *gptr, *bsum, *boff, *dummy;
    cudaGetSymbolAddress((void**)&dis, g_dis);
    cudaGetSymbolAddress((void**)&hw, g_hw);
    cudaGetSymbolAddress((void**)&agg, g_agg);
    cudaGetSymbolAddress((void**)&pm, g_pm);
    cudaGetSymbolAddress((void**)&rowcnt, g_rowcnt);
    cudaGetSymbolAddress((void**)&rowptr, g_rowptr);
    cudaGetSymbolAddress((void**)&fill, g_fill);
    cudaGetSymbolAddress((void**)&esrc, g_esrc);
    cudaGetSymbolAddress((void**)&gcnt, g_gcnt);
    cudaGetSymbolAddress((void**)&gptr, g_gptr);
    cudaGetSymbolAddress((void**)&bsum, g_bsum);
    cudaGetSymbolAddress((void**)&boff, g_boff);
    cudaGetSymbolAddress((void**)&dummy, g_dummy);

    const int* src = ei;
    const int* dst = ei + E;

    // ---- CSR build + norm ----
    k_zero_int<<<(N + 255) / 256, 256>>>(rowcnt, N);
    k_count<<<(E + 255) / 256, 256>>>(dst, rowcnt, E);
    k_dis<<<(N + 255) / 256, 256>>>(rowcnt, dis, N);
    exclusive_scan(rowcnt, N, rowptr, bsum, boff, dummy);
    k_set_int<<<1, 1>>>(rowptr + N, E);
    k_zero_int<<<(N + 255) / 256, 256>>>(fill, N);
    k_csr_fill<<<(E + 255) / 256, 256>>>(src, dst, rowptr, fill, esrc, E);

    // ---- graph segment ptrs (batch is sorted) ----
    k_zero_int<<<(G + 255) / 256, 256>>>(gcnt, G);
    k_count<<<(N + 255) / 256, 256>>>(batch, gcnt, N);
    exclusive_scan(gcnt, G, gptr, bsum, boff, dummy);
    k_set_int<<<1, 1>>>(gptr + G, N);

    // ---- layer 1: a0 = Âx (width 9), z1 = a0@W1, stats, BN1 ----
    k_gather9<<<(N + 255) / 256, 256>>>(x, dis, rowptr, esrc, agg, N);
    k_gemm1<<<(N + 7) / 8, 256>>>(agg, W1, hw, N);
    k_zero_stats<<<1, 128>>>(128);
    k_stats<<<1024, 128>>>(hw, N, 128);
    k_finalize_bn<<<1, 128>>>(gm1, be1, N, 128);

    // ---- layer 2: a1 = Â relu(BN1(z1)) (width 128), z2 = a1@W2 (+stats) ----
    k_gather<128, true><<<(N + 7) / 8, 256>>>(hw, dis, rowptr, esrc, agg, N);
    k_zero_stats<<<1, 256>>>(256);
    {
        dim3 grid(2, (N + 127) / 128);
        k_gemm_mma<true><<<grid, 256>>>(agg, W2, hw, N, 128, 256);
    }
    k_finalize_bn<<<1, 256>>>(gm2, be2, N, 256);

    // ---- layer 3: a2 = Â relu(BN2(z2)) (width 256), z3 = a2@W3 (+stats) ----
    k_gather<256, true><<<(N + 7) / 8, 256>>>(hw, dis, rowptr, esrc, agg, N);
    k_zero_stats<<<1, 256>>>(256);
    {
        dim3 grid(2, (N + 127) / 128);
        k_gemm_mma<true><<<grid, 256>>>(agg, W3, hw, N, 256, 256);
    }
    k_finalize_bn<<<1, 256>>>(gm3, be3, N, 256);

    // ---- pooling over relu(BN3(z3)) ----
    k_pool<<<G, 256>>>(hw, gptr, pm);

    // ---- head (fp32, keeps output precision) ----
    {
        dim3 grid(P / 128, (G + 127) / 128);
        k_sgemm<true><<<grid, 256>>>(pm, Wp, (float*)d_out, G, 256, P, bp);
    }
}

// round 11
// speedup vs baseline: 1.5248x; 1.0230x over previous
#include <cuda_runtime.h>
#include <stdint.h>

#define NMAX 200000
#define EMAX 400000
#define GMAX 8192
#define HMAX 256
#define BN_EPS 1e-5f

// ---------------- scratch (device globals: no allocation allowed) ----------
__device__ float g_dis[NMAX];
__device__ float g_hw[(size_t)NMAX * HMAX];    // z = (Âh) @ W  (GEMM outputs)
__device__ float g_agg[(size_t)NMAX * HMAX];   // a = Â h      (gather outputs)
__device__ float g_colsum[HMAX];
__device__ float g_colsumsq[HMAX];
__device__ float g_scale[HMAX];
__device__ float g_shift[HMAX];
__device__ float g_pm[(size_t)GMAX * HMAX];
__device__ int g_rowcnt[NMAX];
__device__ int g_rowptr[NMAX + 1];
__device__ int g_fill[NMAX];
__device__ int g_esrc[EMAX];
__device__ int g_gcnt[GMAX];
__device__ int g_gptr[GMAX + 1];
__device__ int g_bsum[1024];
__device__ int g_boff[1024];
__device__ int g_dummy[4];

// ---------------- small utility kernels ------------------------------------
__global__ void k_zero_int(int* p, int n) {
    int i = blockIdx.x * blockDim.x + threadIdx.x;
    if (i < n) p[i] = 0;
}
__global__ void k_set_int(int* p, int v) { *p = v; }
__global__ void k_count(const int* __restrict__ idx, int* __restrict__ cnt, int n) {
    int i = blockIdx.x * blockDim.x + threadIdx.x;
    if (i < n) atomicAdd(&cnt[idx[i]], 1);
}
__global__ void k_dis(const int* __restrict__ cnt, float* __restrict__ dis, int n) {
    int i = blockIdx.x * blockDim.x + threadIdx.x;
    if (i < n) dis[i] = rsqrtf((float)cnt[i] + 1.0f);
}

// ---------------- 2-level exclusive scan (chunk = 1024) ---------------------
__global__ void k_scan1(const int* __restrict__ in, int n, int* __restrict__ out,
                        int* __restrict__ bsum) {
    __shared__ int sh[256];
    int t = threadIdx.x;
    int base = blockIdx.x * 1024 + t * 4;
    int v0 = (base + 0 < n) ? in[base + 0] : 0;
    int v1 = (base + 1 < n) ? in[base + 1] : 0;
    int v2 = (base + 2 < n) ? in[base + 2] : 0;
    int v3 = (base + 3 < n) ? in[base + 3] : 0;
    int s = v0 + v1 + v2 + v3;
    sh[t] = s;
    __syncthreads();
    for (int off = 1; off < 256; off <<= 1) {
        int x = (t >= off) ? sh[t - off] : 0;
        __syncthreads();
        sh[t] += x;
        __syncthreads();
    }
    int run = sh[t] - s;
    if (base + 0 < n) out[base + 0] = run; run += v0;
    if (base + 1 < n) out[base + 1] = run; run += v1;
    if (base + 2 < n) out[base + 2] = run; run += v2;
    if (base + 3 < n) out[base + 3] = run;
    if (t == 0) bsum[blockIdx.x] = sh[255];
}
__global__ void k_scan_add(int* __restrict__ out, const int* __restrict__ boff, int n) {
    int i = blockIdx.x * blockDim.x + threadIdx.x;
    if (i < n) out[i] += boff[i >> 10];
}

// ---------------- CSR fill ---------------------------------------------------
__global__ void k_csr_fill(const int* __restrict__ src, const int* __restrict__ dst,
                           const int* __restrict__ rowptr, int* __restrict__ fill,
                           int* __restrict__ esrc, int E) {
    int e = blockIdx.x * blockDim.x + threadIdx.x;
    if (e < E) {
        int d = dst[e];
        int pos = rowptr[d] + atomicAdd(&fill[d], 1);
        esrc[pos] = src[e];
    }
}

// ---------------- width-9 gather: a0 = Â x ----------------------------------
__global__ void k_gather9(const float* __restrict__ x, const float* __restrict__ dis,
                          const int* __restrict__ rowptr, const int* __restrict__ esrc,
                          float* __restrict__ out, int N) {
    int n = blockIdx.x * blockDim.x + threadIdx.x;
    if (n >= N) return;
    float dd = dis[n];
    float a[9];
#pragma unroll
    for (int f = 0; f < 9; f++) a[f] = dd * x[(size_t)n * 9 + f];
    int e0 = rowptr[n], e1 = rowptr[n + 1];
    for (int e = e0; e < e1; e++) {
        int s = esrc[e];
        float w = dis[s];
#pragma unroll
        for (int f = 0; f < 9; f++) a[f] += w * x[(size_t)s * 9 + f];
    }
#pragma unroll
    for (int f = 0; f < 9; f++) out[(size_t)n * 9 + f] = dd * a[f];
}

// ---------------- layer-1 GEMM: [N,9] @ [9,128] -----------------------------
__global__ void k_gemm1(const float* __restrict__ x, const float* __restrict__ W,
                        float* __restrict__ out, int N) {
    __shared__ float Ws[9 * 128];
    __shared__ float xs[8 * 9];
    int tid = threadIdx.x;
    for (int i = tid; i < 9 * 128; i += 256) Ws[i] = W[i];
    int r0 = blockIdx.x * 8;
    if (tid < 72) {
        int rr = tid / 9, cc = tid % 9;
        int r = r0 + rr;
        xs[tid] = (r < N) ? x[(size_t)r * 9 + cc] : 0.0f;
    }
    __syncthreads();
    int lr = tid >> 5;
    int c4 = (tid & 31) * 4;
    int r = r0 + lr;
    if (r >= N) return;
    float a0 = 0.f, a1 = 0.f, a2 = 0.f, a3 = 0.f;
#pragma unroll
    for (int k = 0; k < 9; k++) {
        float xv = xs[lr * 9 + k];
        const float* w = &Ws[k * 128 + c4];
        a0 += xv * w[0]; a1 += xv * w[1]; a2 += xv * w[2]; a3 += xv * w[3];
    }
    *(float4*)&out[(size_t)r * 128 + c4] = make_float4(a0, a1, a2, a3);
}

// ================= tf32 mma.sync GEMM + fused column stats ==================
__device__ __forceinline__ uint32_t f2tf32(float x) {
    uint32_t u; asm("cvt.rna.tf32.f32 %0, %1;" : "=r"(u) : "f"(x)); return u;
}
__device__ __forceinline__ int swz(int k) { return ((k & 3) << 3) | (k >> 2); }

__device__ __forceinline__ void mma_tf32(float4& c, uint32_t a0, uint32_t a1,
                                         uint32_t a2, uint32_t a3,
                                         uint32_t b0, uint32_t b1) {
    asm volatile(
        "mma.sync.aligned.m16n8k8.row.col.f32.tf32.tf32.f32 "
        "{%0,%1,%2,%3}, {%4,%5,%6,%7}, {%8,%9}, {%0,%1,%2,%3};"
        : "+f"(c.x), "+f"(c.y), "+f"(c.z), "+f"(c.w)
        : "r"(a0), "r"(a1), "r"(a2), "r"(a3), "r"(b0), "r"(b1));
}

// C[M,Nc] = A[M,K] @ W[K,Nc]; block tile 128x128, K-chunk 32.
// Register-prefetch double buffering: chunk kc+1 loads overlap chunk kc MMAs.
template <bool STATS>
__global__ void __launch_bounds__(256, 1)
k_gemm_mma(const float* __restrict__ A, const float* __restrict__ W,
           float* __restrict__ C, int M, int K, int Nc) {
    __shared__ uint32_t As[32 * 128];
    __shared__ uint32_t Bs[32 * 128];
    int tid = threadIdx.x;
    int lane = tid & 31, warp = tid >> 5;
    int g = lane >> 2, tig = lane & 3;
    int wm = warp & 3, wn = warp >> 2;
    int rowBase = blockIdx.y * 128;
    int colBase = blockIdx.x * 128;

    // per-thread load coordinates (A: 4 x float4, B: 4 x float4)
    int ar[4], akq[4];
    int bk[4], bn4[4];
#pragma unroll
    for (int l = 0; l < 4; l++) {
        int lin = l * 256 + tid;
        ar[l] = lin >> 3;
        akq[l] = (lin & 7) * 4;
        bk[l] = lin >> 5;
        bn4[l] = (lin & 31) * 4;
    }

    float4 av[4], bv[4];
    // prefetch chunk 0
#pragma unroll
    for (int l = 0; l < 4; l++) {
        int gr = rowBase + ar[l];
        av[l] = make_float4(0.f, 0.f, 0.f, 0.f);
        if (gr < M) av[l] = *(const float4*)&A[(size_t)gr * K + akq[l]];
        bv[l] = *(const float4*)&W[(size_t)bk[l] * Nc + colBase + bn4[l]];
    }

    float4 acc[2][8];
#pragma unroll
    for (int i = 0; i < 2; i++)
#pragma unroll
        for (int j = 0; j < 8; j++) acc[i][j] = make_float4(0.f, 0.f, 0.f, 0.f);

    int nk = K >> 5;
    for (int kc = 0; kc < nk; kc++) {
        // commit prefetched regs to smem
#pragma unroll
        for (int l = 0; l < 4; l++) {
            int r = ar[l], kq = akq[l];
            As[(kq + 0) * 128 + (r ^ swz(kq + 0))] = f2tf32(av[l].x);
            As[(kq + 1) * 128 + (r ^ swz(kq + 1))] = f2tf32(av[l].y);
            As[(kq + 2) * 128 + (r ^ swz(kq + 2))] = f2tf32(av[l].z);
            As[(kq + 3) * 128 + (r ^ swz(kq + 3))] = f2tf32(av[l].w);
            int k = bk[l], n4 = bn4[l];
            int xk = swz(k);
            Bs[k * 128 + ((n4 + 0) ^ xk)] = f2tf32(bv[l].x);
            Bs[k * 128 + ((n4 + 1) ^ xk)] = f2tf32(bv[l].y);
            Bs[k * 128 + ((n4 + 2) ^ xk)] = f2tf32(bv[l].z);
            Bs[k * 128 + ((n4 + 3) ^ xk)] = f2tf32(bv[l].w);
        }
        __syncthreads();
        // prefetch next chunk (overlaps the MMA sequence below)
        if (kc + 1 < nk) {
            int k0 = (kc + 1) * 32;
#pragma unroll
            for (int l = 0; l < 4; l++) {
                int gr = rowBase + ar[l];
                av[l] = make_float4(0.f, 0.f, 0.f, 0.f);
                if (gr < M) av[l] = *(const float4*)&A[(size_t)gr * K + k0 + akq[l]];
                bv[l] = *(const float4*)&W[(size_t)(k0 + bk[l]) * Nc + colBase + bn4[l]];
            }
        }
#pragma unroll
        for (int s = 0; s < 4; s++) {
            int kA = s * 8 + tig;
            int kB = kA + 4;
            int xa = swz(kA), xb = swz(kB);
            uint32_t a[2][4];
#pragma unroll
            for (int mt = 0; mt < 2; mt++) {
                int m = wm * 32 + mt * 16 + g;
                a[mt][0] = As[kA * 128 + (m ^ xa)];
                a[mt][1] = As[kA * 128 + ((m + 8) ^ xa)];
                a[mt][2] = As[kB * 128 + (m ^ xb)];
                a[mt][3] = As[kB * 128 + ((m + 8) ^ xb)];
            }
#pragma unroll
            for (int nt = 0; nt < 8; nt++) {
                int n = wn * 64 + nt * 8 + g;
                uint32_t b0 = Bs[kA * 128 + (n ^ xa)];
                uint32_t b1 = Bs[kB * 128 + (n ^ xb)];
                mma_tf32(acc[0][nt], a[0][0], a[0][1], a[0][2], a[0][3], b0, b1);
                mma_tf32(acc[1][nt], a[1][0], a[1][1], a[1][2], a[1][3], b0, b1);
            }
        }
        __syncthreads();
    }
    // ---- store ----
#pragma unroll
    for (int mt = 0; mt < 2; mt++) {
        int r0 = rowBase + wm * 32 + mt * 16 + g;
#pragma unroll
        for (int nt = 0; nt < 8; nt++) {
            int c = colBase + wn * 64 + nt * 8 + tig * 2;
            if (r0 < M)
                *(float2*)&C[(size_t)r0 * Nc + c] = make_float2(acc[mt][nt].x, acc[mt][nt].y);
            if (r0 + 8 < M)
                *(float2*)&C[(size_t)(r0 + 8) * Nc + c] = make_float2(acc[mt][nt].z, acc[mt][nt].w);
        }
    }
    // ---- fused BN stats ----
    if (STATS) {
#pragma unroll
        for (int nt = 0; nt < 8; nt++) {
            float4 u = acc[0][nt], v = acc[1][nt];
            float s0 = u.x + u.z + v.x + v.z;
            float s1 = u.y + u.w + v.y + v.w;
            float q0 = u.x * u.x + u.z * u.z + v.x * v.x + v.z * v.z;
            float q1 = u.y * u.y + u.w * u.w + v.y * v.y + v.w * v.w;
#pragma unroll
            for (int off = 4; off < 32; off <<= 1) {
                s0 += __shfl_xor_sync(0xffffffffu, s0, off);
                s1 += __shfl_xor_sync(0xffffffffu, s1, off);
                q0 += __shfl_xor_sync(0xffffffffu, q0, off);
                q1 += __shfl_xor_sync(0xffffffffu, q1, off);
            }
            if (lane < 4) {
                int c = colBase + wn * 64 + nt * 8 + lane * 2;
                atomicAdd(&g_colsum[c], s0);
                atomicAdd(&g_colsum[c + 1], s1);
                atomicAdd(&g_colsumsq[c], q0);
                atomicAdd(&g_colsumsq[c + 1], q1);
            }
        }
    }
}

// ---------------- CSR gather: warp per (node, 128-col slice), pipelined ------
// out[d, slice] = dis[d] * ( sum_e dis[s]*f(hw[s]) + dis[d]*f(hw[d]) )
template <int H, bool BN>
__global__ void k_gather(const float* __restrict__ hw, const float* __restrict__ dis,
                         const int* __restrict__ rowptr, const int* __restrict__ esrc,
                         float* __restrict__ agg, int N) {
    constexpr int S = H / 128;
    int w = (blockIdx.x * blockDim.x + threadIdx.x) >> 5;
    int lane = threadIdx.x & 31;
    int n = (S == 1) ? w : (w >> 1);
    int sl = (S == 1) ? 0 : (w & 1);
    if (n >= N) return;
    int c = sl * 128 + lane * 4;

    float4 sc, sh;
    if (BN) {
        sc = *(const float4*)&g_scale[c];
        sh = *(const float4*)&g_shift[c];
    }
    int e0 = __ldg(&rowptr[n]), e1 = __ldg(&rowptr[n + 1]);
    float dd = __ldg(&dis[n]);

    float4 acc = make_float4(0.f, 0.f, 0.f, 0.f);
    int s_nxt = 0; float w_nxt = 0.f;
    if (e0 < e1) { s_nxt = __ldg(&esrc[e0]); w_nxt = __ldg(&dis[s_nxt]); }
    for (int e = e0; e < e1; e++) {
        int s = s_nxt; float ws = w_nxt;
        if (e + 1 < e1) { s_nxt = __ldg(&esrc[e + 1]); w_nxt = __ldg(&dis[s_nxt]); }
        float4 x = __ldg((const float4*)&hw[(size_t)s * H + c]);
        if (BN) {
            x.x = fmaxf(x.x * sc.x + sh.x, 0.f);
            x.y = fmaxf(x.y * sc.y + sh.y, 0.f);
            x.z = fmaxf(x.z * sc.z + sh.z, 0.f);
            x.w = fmaxf(x.w * sc.w + sh.w, 0.f);
        }
        acc.x += ws * x.x; acc.y += ws * x.y;
        acc.z += ws * x.z; acc.w += ws * x.w;
    }
    float4 x = __ldg((const float4*)&hw[(size_t)n * H + c]);
    if (BN) {
        x.x = fmaxf(x.x * sc.x + sh.x, 0.f);
        x.y = fmaxf(x.y * sc.y + sh.y, 0.f);
        x.z = fmaxf(x.z * sc.z + sh.z, 0.f);
        x.w = fmaxf(x.w * sc.w + sh.w, 0.f);
    }
    float4 r;
    r.x = dd * (acc.x + dd * x.x);
    r.y = dd * (acc.y + dd * x.y);
    r.z = dd * (acc.z + dd * x.z);
    r.w = dd * (acc.w + dd * x.w);
    *(float4*)&agg[(size_t)n * H + c] = r;
}

// ---------------- BN stats (layer-1 only) ------------------------------------
__global__ void k_stats(const float* __restrict__ agg, int N, int H) {
    int c = threadIdx.x;
    float s = 0.f, ss = 0.f;
    for (int r = blockIdx.x; r < N; r += gridDim.x) {
        float v = agg[(size_t)r * H + c];
        s += v; ss += v * v;
    }
    atomicAdd(&g_colsum[c], s);
    atomicAdd(&g_colsumsq[c], ss);
}
__global__ void k_zero_stats(int H) {
    int c = threadIdx.x;
    if (c < H) { g_colsum[c] = 0.f; g_colsumsq[c] = 0.f; }
}
__global__ void k_finalize_bn(const float* __restrict__ gam, const float* __restrict__ bet,
                              int N, int H) {
    int c = threadIdx.x;
    if (c >= H) return;
    float inv = 1.0f / (float)N;
    float mean = g_colsum[c] * inv;
    float var = fmaxf(g_colsumsq[c] * inv - mean * mean, 0.f);
    float sc = gam[c] * rsqrtf(var + BN_EPS);
    g_scale[c] = sc;
    g_shift[c] = bet[c] - mean * sc;
}

// ---------------- fp32 SGEMM (head only) with packed f32x2 -------------------
__device__ __forceinline__ unsigned long long dup_f32x2(float a) {
    unsigned long long r;
    unsigned int u = __float_as_uint(a);
    asm("mov.b64 %0, {%1, %1};" : "=l"(r) : "r"(u));
    return r;
}
__device__ __forceinline__ void fma2(unsigned long long& acc, unsigned long long a,
                                     unsigned long long b) {
    asm("fma.rn.f32x2 %0, %1, %2, %0;" : "+l"(acc) : "l"(a), "l"(b));
}
union F4U2 { float4 f; unsigned long long u[2]; };

template <bool BIAS>
__global__ void __launch_bounds__(256)
k_sgemm(const float* __restrict__ A, const float* __restrict__ W,
        float* __restrict__ C, int M, int K, int Nc,
        const float* __restrict__ bias) {
    __shared__ float As[16][132];
    __shared__ float Ws[16][128];
    int tid = threadIdx.x;
    int tx = tid & 15;
    int ty = tid >> 4;
    int rowBase = blockIdx.y * 128;
    int colBase = blockIdx.x * 128;

    unsigned long long acc2[8][4];
#pragma unroll
    for (int i = 0; i < 8; i++)
#pragma unroll
        for (int j = 0; j < 4; j++) acc2[i][j] = 0ULL;

    for (int k0 = 0; k0 < K; k0 += 16) {
#pragma unroll
        for (int l = 0; l < 2; l++) {
            int lin = tid + l * 256;
            int ar = lin >> 2;
            int ac = (lin & 3) * 4;
            int r = rowBase + ar;
            float4 v = make_float4(0.f, 0.f, 0.f, 0.f);
            if (r < M) v = *(const float4*)&A[(size_t)r * K + k0 + ac];
            As[ac + 0][ar] = v.x; As[ac + 1][ar] = v.y;
            As[ac + 2][ar] = v.z; As[ac + 3][ar] = v.w;
        }
#pragma unroll
        for (int l = 0; l < 2; l++) {
            int lin = tid + l * 256;
            int wr = lin >> 5;
            int wc = (lin & 31) * 4;
            *(float4*)&Ws[wr][wc] = *(const float4*)&W[(size_t)(k0 + wr) * Nc + colBase + wc];
        }
        __syncthreads();
#pragma unroll
        for (int k = 0; k < 16; k++) {
            F4U2 a0, a1, b0, b1;
            a0.f = *(float4*)&As[k][ty * 8];
            a1.f = *(float4*)&As[k][ty * 8 + 4];
            b0.f = *(float4*)&Ws[k][tx * 8];
            b1.f = *(float4*)&Ws[k][tx * 8 + 4];
            float av[8] = {a0.f.x, a0.f.y, a0.f.z, a0.f.w, a1.f.x, a1.f.y, a1.f.z, a1.f.w};
            unsigned long long bp[4] = {b0.u[0], b0.u[1], b1.u[0], b1.u[1]};
#pragma unroll
            for (int i = 0; i < 8; i++) {
                unsigned long long ad = dup_f32x2(av[i]);
#pragma unroll
                for (int jp = 0; jp < 4; jp++) fma2(acc2[i][jp], ad, bp[jp]);
            }
        }
        __syncthreads();
    }
#pragma unroll
    for (int i = 0; i < 8; i++) {
        int r = rowBase + ty * 8 + i;
        if (r >= M) continue;
#pragma unroll
        for (int jp = 0; jp < 4; jp += 2) {
            int c = colBase + tx * 8 + jp * 2;
            unsigned long long u0 = acc2[i][jp], u1 = acc2[i][jp + 1];
            float4 v;
            v.x = __uint_as_float((unsigned)u0);
            v.y = __uint_as_float((unsigned)(u0 >> 32));
            v.z = __uint_as_float((unsigned)u1);
            v.w = __uint_as_float((unsigned)(u1 >> 32));
            if (BIAS) { v.x += bias[c]; v.y += bias[c + 1]; v.z += bias[c + 2]; v.w += bias[c + 3]; }
            *(float4*)&C[(size_t)r * Nc + c] = v;
        }
    }
}

// ---------------- segmented pooling (BN3+ReLU fused) --------------------------
__global__ void k_pool(const float* __restrict__ agg, const int* __restrict__ gptr,
                       float* __restrict__ pm) {
    int g = blockIdx.x;
    int c = threadIdx.x;
    int r0 = gptr[g], r1 = gptr[g + 1];
    float sc = g_scale[c], sh = g_shift[c];
    float s = 0.f;
    for (int r = r0; r < r1; r++) {
        float v = agg[(size_t)r * 256 + c];
        s += fmaxf(v * sc + sh, 0.f);
    }
    float cnt = (float)(r1 - r0);
    pm[(size_t)g * 256 + c] = s / fmaxf(cnt, 1.0f);
}

// ---------------- host driver ------------------------------------------------
static void exclusive_scan(int* data_in, int n, int* out, int* bsum, int* boff, int* dummy) {
    int nb = (n + 1023) / 1024;
    k_scan1<<<nb, 256>>>(data_in, n, out, bsum);
    k_scan1<<<1, 256>>>(bsum, nb, boff, dummy);
    k_scan_add<<<(n + 255) / 256, 256>>>(out, boff, n);
}

extern "C" void kernel_launch(void* const* d_in, const int* in_sizes, int n_in,
                              void* d_out, int out_size) {
    const float* x = (const float*)d_in[0];
    const int* ei = (const int*)d_in[1];
    const int* batch = (const int*)d_in[2];
    int o = (in_sizes[3] == 1) ? 4 : 3;
    const float* W1 = (const float*)d_in[o + 0];
    const float* gm1 = (const float*)d_in[o + 2];
    const float* be1 = (const float*)d_in[o + 3];
    const float* W2 = (const float*)d_in[o + 4];
    const float* gm2 = (const float*)d_in[o + 6];
    const float* be2 = (const float*)d_in[o + 7];
    const float* W3 = (const float*)d_in[o + 8];
    const float* gm3 = (const float*)d_in[o + 10];
    const float* be3 = (const float*)d_in[o + 11];
    const float* Wp = (const float*)d_in[o + 12];
    const float* bp = (const float*)d_in[o + 13];

    int N = in_sizes[0] / 9;
    int E = in_sizes[1] / 2;
    int P = in_sizes[o + 13];
    int G = out_size / P;

    float *dis, *hw, *agg, *pm;
    int *rowcnt, *rowptr, *fill, *esrc, *gcnt, *gptr, *bsum, *boff, *dummy;
    cudaGetSymbolAddress((void**)&dis, g_dis);
    cudaGetSymbolAddress((void**)&hw, g_hw);
    cudaGetSymbolAddress((void**)&agg, g_agg);
    cudaGetSymbolAddress((void**)&pm, g_pm);
    cudaGetSymbolAddress((void**)&rowcnt, g_rowcnt);
    cudaGetSymbolAddress((void**)&rowptr, g_rowptr);
    cudaGetSymbolAddress((void**)&fill, g_fill);
    cudaGetSymbolAddress((void**)&esrc, g_esrc);
    cudaGetSymbolAddress((void**)&gcnt, g_gcnt);
    cudaGetSymbolAddress((void**)&gptr, g_gptr);
    cudaGetSymbolAddress((void**)&bsum, g_bsum);
    cudaGetSymbolAddress((void**)&boff, g_boff);
    cudaGetSymbolAddress((void**)&dummy, g_dummy);

    const int* src = ei;
    const int* dst = ei + E;

    // ---- CSR build + norm ----
    k_zero_int<<<(N + 255) / 256, 256>>>(rowcnt, N);
    k_count<<<(E + 255) / 256, 256>>>(dst, rowcnt, E);
    k_dis<<<(N + 255) / 256, 256>>>(rowcnt, dis, N);
    exclusive_scan(rowcnt, N, rowptr, bsum, boff, dummy);
    k_set_int<<<1, 1>>>(rowptr + N, E);
    k_zero_int<<<(N + 255) / 256, 256>>>(fill, N);
    k_csr_fill<<<(E + 255) / 256, 256>>>(src, dst, rowptr, fill, esrc, E);

    // ---- graph segment ptrs (batch is sorted) ----
    k_zero_int<<<(G + 255) / 256, 256>>>(gcnt, G);
    k_count<<<(N + 255) / 256, 256>>>(batch, gcnt, N);
    exclusive_scan(gcnt, G, gptr, bsum, boff, dummy);
    k_set_int<<<1, 1>>>(gptr + G, N);

    // ---- layer 1: a0 = Âx (width 9), z1 = a0@W1, stats, BN1 ----
    k_gather9<<<(N + 255) / 256, 256>>>(x, dis, rowptr, esrc, agg, N);
    k_gemm1<<<(N + 7) / 8, 256>>>(agg, W1, hw, N);
    k_zero_stats<<<1, 128>>>(128);
    k_stats<<<1024, 128>>>(hw, N, 128);
    k_finalize_bn<<<1, 128>>>(gm1, be1, N, 128);

    // ---- layer 2: a1 = Â relu(BN1(z1)) (width 128), z2 = a1@W2 (+stats) ----
    k_gather<128, true><<<(N + 7) / 8, 256>>>(hw, dis, rowptr, esrc, agg, N);
    k_zero_stats<<<1, 256>>>(256);
    {
        dim3 grid(2, (N + 127) / 128);
        k_gemm_mma<true><<<grid, 256>>>(agg, W2, hw, N, 128, 256);
    }
    k_finalize_bn<<<1, 256>>>(gm2, be2, N, 256);

    // ---- layer 3: a2 = Â relu(BN2(z2)) (width 256, 2 warps/node), z3 ----
    k_gather<256, true><<<(2 * N + 7) / 8, 256>>>(hw, dis, rowptr, esrc, agg, N);
    k_zero_stats<<<1, 256>>>(256);
    {
        dim3 grid(2, (N + 127) / 128);
        k_gemm_mma<true><<<grid, 256>>>(agg, W3, hw, N, 256, 256);
    }
    k_finalize_bn<<<1, 256>>>(gm3, be3, N, 256);

    // ---- pooling over relu(BN3(z3)) ----
    k_pool<<<G, 256>>>(hw, gptr, pm);

    // ---- head (fp32, keeps output precision) ----
    {
        dim3 grid(P / 128, (G + 127) / 128);
        k_sgemm<true><<<grid, 256>>>(pm, Wp, (float*)d_out, G, 256, P, bp);
    }
}